// round 7
// baseline (speedup 1.0000x reference)
#include <cuda_runtime.h>
#include <cstdint>

// VoltageNet R6: one CTA/batch, 512 thr, 16 steps/thr, 2 CTAs/SM.
// Key idea: per-step MLP+OCV is a univariate function of SOC; within a batch
// SOC spans only ~0.02. Build a 512-entry per-CTA table over the block's
// actual SOC range (1 transcendental eval/thread), then inner loop = lerp.
// sAB staged TRANSPOSED (k*NT+tid) -> conflict-free (R5's 32-way conflict fix).

#define TT 8192
#define NT 512
#define LL 16
#define NTAB 512
#define FULL 0xFFFFFFFFu
// dynamic smem: float2 sAB[TT] (64KB) + float4 sTab[NTAB] (8KB)
#define SMEM_BYTES ((2 * TT + 4 * NTAB) * 4)

__device__ __forceinline__ float tanh_fast(float x) {
    float y; asm("tanh.approx.f32 %0, %1;" : "=f"(y) : "f"(x)); return y;
}
__device__ __forceinline__ float sigmoid_f(float z) {
    return fmaf(tanh_fast(0.5f * z), 0.5f, 0.5f);
}
__device__ __forceinline__ float softplus_f(float x) {
    return fmaxf(x, 0.0f) + __logf(1.0f + __expf(-fabsf(x)));
}

__global__ __launch_bounds__(NT, 2)
void voltage_kernel(const float* __restrict__ X, const float* __restrict__ SC,
                    const float* __restrict__ W1g, const float* __restrict__ b1g,
                    const float* __restrict__ W2g, const float* __restrict__ b2g,
                    float* __restrict__ out)
{
    extern __shared__ float smem[];
    float2* sAB = reinterpret_cast<float2*>(smem);        // [k*NT+tid]: (I,ds) then (a,b)
    float4* sTab = reinterpret_cast<float4*>(smem + 2 * TT); // (ocv, C, R1C, th2)

    __shared__ float sWS[16], sWA[16], sWB[16], sTr[16], sMnA[16], sMxA[16];
    __shared__ float sW10[6], sC1[6], sW2[30], sB2[5];
    __shared__ float sTmean, sU10, sMn, sInvD;

    const int tid  = threadIdx.x;
    const int lane = tid & 31;
    const int wid  = tid >> 5;
    const int b    = blockIdx.x;
    const int base = tid * LL;

    const float Q  = SC[2 * b + 0];
    const float R0 = SC[2 * b + 1];

    // stage MLP constants: W1 col-0 weights, W2 cols {0,1,2,5,6}, matching b2
    if (tid < 6) sW10[tid] = W1g[tid];
    if (tid >= 32 && tid < 62) {
        int i = (tid - 32) / 5, c = (tid - 32) % 5;
        const int col[5] = {0, 1, 2, 5, 6};
        sW2[tid - 32] = W2g[i * 7 + col[c]];
    }
    if (tid >= 64 && tid < 69) {
        const int col[5] = {0, 1, 2, 5, 6};
        sB2[tid - 64] = b2g[col[tid - 64]];
    }

    // ---------- phase 0: load 16 steps (two 6xfloat4 chunks), stage (I, ds) ----------
    const float invC = 1.0f / 36000.0f;   // 1/(2*3600*QN), QN=5
    float tsum = 0.0f, dsum = 0.0f;
    float rmn = 0.0f, rmx = 0.0f;         // local soc excursion (relative to start)
    float pt = 0.0f, pI = 0.0f;
    {
        const float4* px = reinterpret_cast<const float4*>(X + ((size_t)b * TT + base) * 3);
#pragma unroll
        for (int c = 0; c < 2; c++) {
            float4 v[6];
#pragma unroll
            for (int i = 0; i < 6; i++) v[i] = px[c * 6 + i];
            const float* f = reinterpret_cast<const float*>(v);
#pragma unroll
            for (int j = 0; j < 8; j++) {
                int s = c * 8 + j;
                float t = f[3 * j], I = f[3 * j + 1], Te = f[3 * j + 2];
                tsum += Te;
                if (s > 0) {
                    float d = (I + pI) * (t - pt) * invC;
                    dsum += d;                       // running cum AFTER step s-1
                    rmn = fminf(rmn, dsum);
                    rmx = fmaxf(rmx, dsum);
                    sAB[(s - 1) * NT + tid] = make_float2(pI, d);
                }
                pt = t; pI = I;
            }
        }
    }
    float t16 = pt, I16 = pI;             // clamp at end -> ds=0, a=1, b=0
    if (tid < NT - 1) {
        float2 e = *reinterpret_cast<const float2*>(X + ((size_t)b * TT + base + LL) * 3);
        t16 = e.x; I16 = e.y;
    }
    {
        float d = (I16 + pI) * (t16 - pt) * invC;
        dsum += d;
        sAB[(LL - 1) * NT + tid] = make_float2(pI, d);
        // note: soc at step 15 is start+cum_15 (already covered by rmn/rmx above,
        // since cum_15 was the value of dsum before this last add)
    }

    // ---------- block scan of dsum; reduce tsum / min / max ----------
    float v = dsum;
#pragma unroll
    for (int o = 1; o < 32; o <<= 1) {
        float n = __shfl_up_sync(FULL, v, o);
        if (lane >= o) v += n;
    }
    float excl = __shfl_up_sync(FULL, v, 1);
    if (lane == 0) excl = 0.0f;
#pragma unroll
    for (int o = 16; o > 0; o >>= 1) tsum += __shfl_down_sync(FULL, tsum, o);
    if (lane == 31) sWS[wid] = v;
    if (lane == 0)  sTr[wid] = tsum;
    __syncthreads();

    if (tid < 32) {
        float w = (lane < 16) ? sWS[lane] : 0.0f;
#pragma unroll
        for (int o = 1; o < 16; o <<= 1) {
            float n = __shfl_up_sync(FULL, w, o);
            if (lane >= o) w += n;
        }
        float e = __shfl_up_sync(FULL, w, 1);
        if (lane == 0) e = 0.0f;
        if (lane < 16) sWS[lane] = e;
        float ts = (lane < 16) ? sTr[lane] : 0.0f;
#pragma unroll
        for (int o = 16; o > 0; o >>= 1) ts += __shfl_down_sync(FULL, ts, o);
        if (lane == 0) sTmean = ts * (1.0f / TT);
    }
    __syncthreads();

    // thread-absolute soc extremes now that start is known
    float start = fmaf(Q, 0.2f, sWS[wid] + excl);
    float tMn = start + rmn, tMx = start + rmx;
#pragma unroll
    for (int o = 16; o > 0; o >>= 1) {
        tMn = fminf(tMn, __shfl_down_sync(FULL, tMn, o));
        tMx = fmaxf(tMx, __shfl_down_sync(FULL, tMx, o));
    }
    if (lane == 0) { sMnA[wid] = tMn; sMxA[wid] = tMx; }
    if (tid < 6)
        sC1[tid] = fmaf(R0, W1g[6 + tid], fmaf(sTmean, W1g[12 + tid], b1g[tid]));
    __syncthreads();
    if (tid < 32) {
        float mn = (lane < 16) ? sMnA[lane] : 3.4e38f;
        float mx = (lane < 16) ? sMxA[lane] : -3.4e38f;
#pragma unroll
        for (int o = 16; o > 0; o >>= 1) {
            mn = fminf(mn, __shfl_down_sync(FULL, mn, o));
            mx = fmaxf(mx, __shfl_down_sync(FULL, mx, o));
        }
        if (lane == 0) {
            mn -= 1e-5f; mx += 1e-5f;
            sMn = mn;
            sInvD = (float)(NTAB - 1) / (mx - mn);
        }
    }
    __syncthreads();

    // ---------- table build: 1 MLP+OCV eval per thread ----------
    {
        float mn = sMn;
        float delta = __fdividef(1.0f, sInvD);
        float se = fmaf((float)tid, delta, mn);
        float p0 = sB2[0], p1 = sB2[1], p2 = sB2[2], p5 = sB2[3], p6 = sB2[4];
#pragma unroll
        for (int j = 0; j < 6; j++) {
            float h = softplus_f(fmaf(se, sW10[j], sC1[j]));
            p0 = fmaf(h, sW2[j * 5 + 0], p0);
            p1 = fmaf(h, sW2[j * 5 + 1], p1);
            p2 = fmaf(h, sW2[j * 5 + 2], p2);
            p5 = fmaf(h, sW2[j * 5 + 3], p5);
            p6 = fmaf(h, sW2[j * 5 + 4], p6);
        }
        float R1  = 0.04f * sigmoid_f(0.01f * p0);
        float C   = 1e-6f * sigmoid_f(0.01f * p1);
        float th2 = fmaf(0.75f, sigmoid_f(0.01f * p2), 0.05f);
        float ox  = fmaf(0.79764f, sigmoid_f(0.01f * p5), 0.04236f);
        float oy  = fmaf(0.82504f, sigmoid_f(0.01f * p6), 0.023f);

        float up = 4.4167f + oy * (-1.6518f + oy * (1.6225f + oy * (-2.0843f + oy * (3.5146f + oy * (-2.2166f)))));
        up -= 4.0f * __expf(fmaf(109.451f, oy, -100.006f));
        float un = 0.063f + 0.8f * __expf(-75.0f * (ox + 0.001f));
        un -= 0.012f  * tanh_fast(fmaf(ox, 62.5f, -7.9375f));
        un -= 0.0118f * tanh_fast(fmaf(ox, 62.5f, -9.6875f));
        un -= 0.0035f * tanh_fast(fmaf(ox, 50.0f, -11.0f));
        un -= 0.0095f * tanh_fast(fmaf(ox, 76.923076923f, -14.6153846154f));
        un -= 0.0145f * tanh_fast(fmaf(ox, 50.0f, -24.5f));
        un -= 0.08f   * tanh_fast(fmaf(ox, 18.1818181818f, -18.7272727273f));

        sTab[tid] = make_float4(up - un, C, R1 * C, th2);
    }
    __syncthreads();

    // U1(0) from table th2 at soc0 = Q*0.2 (== thread 0's start, in range)
    if (tid == 0) {
        float u = (Q * 0.2f - sMn) * sInvD;
        u = fminf(fmaxf(u, 0.0f), (float)(NTAB - 1) - 1e-3f);
        int i = (int)u; float fr = u - (float)i;
        float th2 = sTab[i].w + fr * (sTab[i + 1].w - sTab[i].w);
        sU10 = -th2 - sAB[0].x * R0;
    }

    // ---------- phase 1: lerp table; v[k] = OCV + I*R0; (a,b) -> sAB; compose ----------
    const float mn = sMn, invD = sInvD;
    float soc = start;
    float A = 1.0f, Bc = 0.0f;
    float vOC[LL];
    float2 cur = sAB[tid];
#pragma unroll
    for (int k = 0; k < LL; k++) {
        float2 nxt = (k < LL - 1) ? sAB[(k + 1) * NT + tid] : make_float2(I16, 0.0f);
        float Ik = cur.x, dsk = cur.y;

        float u = (soc - mn) * invD;
        u = fminf(fmaxf(u, 0.0f), (float)(NTAB - 1) - 1e-3f);
        int i = (int)u; float fr = u - (float)i;
        float4 t0 = sTab[i];
        float4 t1 = sTab[i + 1];
        float ocv = t0.x + fr * (t1.x - t0.x);
        float C   = t0.y + fr * (t1.y - t0.y);
        float R1C = t0.z + fr * (t1.z - t0.z);

        vOC[k] = ocv + Ik * R0;

        float dt = nxt.x - Ik;
        float a  = 1.0f - dt * C;
        float bb = dt * R1C * Ik;
        sAB[k * NT + tid] = make_float2(a, bb);
        Bc = fmaf(a, Bc, bb);
        A *= a;

        soc += dsk;
        cur = nxt;
    }

    // ---------- phase 2: block affine scan over (A,B) ----------
#pragma unroll
    for (int o = 1; o < 32; o <<= 1) {
        float Ao = __shfl_up_sync(FULL, A, o);
        float Bo = __shfl_up_sync(FULL, Bc, o);
        if (lane >= o) { Bc = fmaf(A, Bo, Bc); A = A * Ao; }
    }
    float Ax = __shfl_up_sync(FULL, A, 1);
    float Bx = __shfl_up_sync(FULL, Bc, 1);
    if (lane == 0) { Ax = 1.0f; Bx = 0.0f; }
    if (lane == 31) { sWA[wid] = A; sWB[wid] = Bc; }
    __syncthreads();
    if (tid < 32) {
        float wA = (lane < 16) ? sWA[lane] : 1.0f;
        float wB = (lane < 16) ? sWB[lane] : 0.0f;
#pragma unroll
        for (int o = 1; o < 16; o <<= 1) {
            float Ao = __shfl_up_sync(FULL, wA, o);
            float Bo = __shfl_up_sync(FULL, wB, o);
            if (lane >= o) { wB = fmaf(wA, Bo, wB); wA = wA * Ao; }
        }
        float eA = __shfl_up_sync(FULL, wA, 1);
        float eB = __shfl_up_sync(FULL, wB, 1);
        if (lane == 0) { eA = 1.0f; eB = 0.0f; }
        if (lane < 16) { sWA[lane] = eA; sWB[lane] = eB; }
    }
    __syncthreads();
    float wA = sWA[wid], wB = sWB[wid];
    float EA = Ax * wA;
    float EB = fmaf(Ax, wB, Bx);
    float U1 = fmaf(EA, sU10, EB);

    // ---------- phase 3: replay U1, direct store ----------
    float* ob = out + (size_t)b * TT + base;
#pragma unroll
    for (int k = 0; k < LL; k++) {
        float2 ab = sAB[k * NT + tid];
        ob[k] = vOC[k] + U1;
        U1 = fmaf(ab.x, U1, ab.y);
    }
}

extern "C" void kernel_launch(void* const* d_in, const int* in_sizes, int n_in,
                              void* d_out, int out_size)
{
    const float* X  = (const float*)d_in[0];
    const float* SC = (const float*)d_in[1];
    const float* W1 = (const float*)d_in[2];
    const float* b1 = (const float*)d_in[3];
    const float* W2 = (const float*)d_in[4];
    const float* b2 = (const float*)d_in[5];
    int B = in_sizes[1] / 2;   // SC is (B,2)
    cudaFuncSetAttribute(voltage_kernel,
                         cudaFuncAttributeMaxDynamicSharedMemorySize, SMEM_BYTES);
    voltage_kernel<<<B, NT, SMEM_BYTES>>>(X, SC, W1, b1, W2, b2, (float*)d_out);
}

// round 8
// speedup vs baseline: 2.0523x; 2.0523x over previous
#include <cuda_runtime.h>
#include <cstdint>

// VoltageNet R7: one CTA/batch, 512 thr, 16 steps/thr, 2 CTAs/SM.
// MLP+OCV is univariate in SOC -> 32-entry WARP-REGISTER table (lane l holds
// entry l), lookup by __shfl_sync (no smem, no conflicts). (I,ds)/(a,b) staged
// transposed in smem; output staged in skewed sV for coalesced STG (R6 fix).

#define TT 8192
#define NT 512
#define LL 16
#define FULL 0xFFFFFFFFu
// dynamic smem: float2 sID[TT] (64KB) + float sV[TT + TT/16] (34.8KB)
#define SMEM_BYTES ((2 * TT + TT + TT / 16) * 4)

__device__ __forceinline__ float tanh_fast(float x) {
    float y; asm("tanh.approx.f32 %0, %1;" : "=f"(y) : "f"(x)); return y;
}
__device__ __forceinline__ float sigmoid_f(float z) {
    return fmaf(tanh_fast(0.5f * z), 0.5f, 0.5f);
}
__device__ __forceinline__ float softplus_f(float x) {
    return fmaxf(x, 0.0f) + __logf(1.0f + __expf(-fabsf(x)));
}

__global__ __launch_bounds__(NT, 2)
void voltage_kernel(const float* __restrict__ X, const float* __restrict__ SC,
                    const float* __restrict__ W1g, const float* __restrict__ b1g,
                    const float* __restrict__ W2g, const float* __restrict__ b2g,
                    float* __restrict__ out)
{
    extern __shared__ float smem[];
    float2* sID = reinterpret_cast<float2*>(smem);   // [k*NT+tid]: (I,ds) then (a,b)
    float*  sV  = smem + 2 * TT;                     // skewed: slot(t) = t + (t>>4)

    __shared__ float sWS[16], sWA[16], sWB[16], sTr[16], sMnA[16], sMxA[16];
    __shared__ float sW10[6], sC1[6], sW2[24], sB2[4];
    __shared__ float sTmean, sU10, sMn, sInvD, sDelta;

    const int tid  = threadIdx.x;
    const int lane = tid & 31;
    const int wid  = tid >> 5;
    const int b    = blockIdx.x;
    const int base = tid * LL;

    const float Q  = SC[2 * b + 0];
    const float R0 = SC[2 * b + 1];

    // stage MLP constants (W1 soc-col; W2 cols {0,1,5,6})
    if (tid < 6) sW10[tid] = W1g[tid];
    if (tid >= 32 && tid < 56) {
        int i = (tid - 32) >> 2, c = (tid - 32) & 3;
        const int col[4] = {0, 1, 5, 6};
        sW2[tid - 32] = W2g[i * 7 + col[c]];
    }
    if (tid >= 64 && tid < 68) {
        const int col[4] = {0, 1, 5, 6};
        sB2[tid - 64] = b2g[col[tid - 64]];
    }

    // ---------- phase 0: load 16 steps (two 6xfloat4 chunks), stage (I, ds) ----------
    const float invC = 1.0f / 36000.0f;   // 1/(2*3600*QN), QN=5
    float tsum = 0.0f, dsum = 0.0f;
    float rmn = 0.0f, rmx = 0.0f;         // soc excursion relative to thread start
    float pt = 0.0f, pI = 0.0f;
    {
        const float4* px = reinterpret_cast<const float4*>(X + ((size_t)b * TT + base) * 3);
#pragma unroll
        for (int c = 0; c < 2; c++) {
            float4 v[6];
#pragma unroll
            for (int i = 0; i < 6; i++) v[i] = px[c * 6 + i];
            const float* f = reinterpret_cast<const float*>(v);
#pragma unroll
            for (int j = 0; j < 8; j++) {
                int s = c * 8 + j;
                float t = f[3 * j], I = f[3 * j + 1], Te = f[3 * j + 2];
                tsum += Te;
                if (s > 0) {
                    float d = (I + pI) * (t - pt) * invC;
                    dsum += d;
                    rmn = fminf(rmn, dsum);
                    rmx = fmaxf(rmx, dsum);
                    sID[(s - 1) * NT + tid] = make_float2(pI, d);
                }
                pt = t; pI = I;
            }
        }
    }
    float t16 = pt, I16 = pI;             // clamp at end -> ds=0, a=1, b=0
    if (tid < NT - 1) {
        float2 e = *reinterpret_cast<const float2*>(X + ((size_t)b * TT + base + LL) * 3);
        t16 = e.x; I16 = e.y;
    }
    {
        float d = (I16 + pI) * (t16 - pt) * invC;
        dsum += d;
        sID[(LL - 1) * NT + tid] = make_float2(pI, d);
    }

    // ---------- block scan of dsum; reduce tsum ----------
    float v = dsum;
#pragma unroll
    for (int o = 1; o < 32; o <<= 1) {
        float n = __shfl_up_sync(FULL, v, o);
        if (lane >= o) v += n;
    }
    float excl = __shfl_up_sync(FULL, v, 1);
    if (lane == 0) excl = 0.0f;
#pragma unroll
    for (int o = 16; o > 0; o >>= 1) tsum += __shfl_down_sync(FULL, tsum, o);
    if (lane == 31) sWS[wid] = v;
    if (lane == 0)  sTr[wid] = tsum;
    __syncthreads();

    if (tid < 32) {
        float w = (lane < 16) ? sWS[lane] : 0.0f;
#pragma unroll
        for (int o = 1; o < 16; o <<= 1) {
            float n = __shfl_up_sync(FULL, w, o);
            if (lane >= o) w += n;
        }
        float e = __shfl_up_sync(FULL, w, 1);
        if (lane == 0) e = 0.0f;
        if (lane < 16) sWS[lane] = e;
        float ts = (lane < 16) ? sTr[lane] : 0.0f;
#pragma unroll
        for (int o = 16; o > 0; o >>= 1) ts += __shfl_down_sync(FULL, ts, o);
        if (lane == 0) sTmean = ts * (1.0f / TT);
    }
    __syncthreads();

    // absolute soc extremes; hidden-layer bias with Tmean/R0 folded
    const float start = fmaf(Q, 0.2f, sWS[wid] + excl);
    {
        float tMn = start + rmn, tMx = start + rmx;
#pragma unroll
        for (int o = 16; o > 0; o >>= 1) {
            tMn = fminf(tMn, __shfl_down_sync(FULL, tMn, o));
            tMx = fmaxf(tMx, __shfl_down_sync(FULL, tMx, o));
        }
        if (lane == 0) { sMnA[wid] = tMn; sMxA[wid] = tMx; }
    }
    if (tid < 6)
        sC1[tid] = fmaf(R0, W1g[6 + tid], fmaf(sTmean, W1g[12 + tid], b1g[tid]));
    __syncthreads();
    if (tid < 32) {
        float mn = (lane < 16) ? sMnA[lane] : 3.4e38f;
        float mx = (lane < 16) ? sMxA[lane] : -3.4e38f;
#pragma unroll
        for (int o = 16; o > 0; o >>= 1) {
            mn = fminf(mn, __shfl_down_sync(FULL, mn, o));
            mx = fmaxf(mx, __shfl_down_sync(FULL, mx, o));
        }
        if (lane == 0) {
            mn -= 1e-5f; mx += 1e-5f;
            sMn = mn;
            sInvD = 31.0f / (mx - mn);
            sDelta = (mx - mn) * (1.0f / 31.0f);
        }
    }
    __syncthreads();

    // ---------- per-warp register table: lane l holds entry l ----------
    float tabO, tabC, tabR;
    {
        float se = fmaf((float)lane, sDelta, sMn);
        float p0 = sB2[0], p1 = sB2[1], p5 = sB2[2], p6 = sB2[3];
#pragma unroll
        for (int j = 0; j < 6; j++) {
            float h = softplus_f(fmaf(se, sW10[j], sC1[j]));
            p0 = fmaf(h, sW2[j * 4 + 0], p0);
            p1 = fmaf(h, sW2[j * 4 + 1], p1);
            p5 = fmaf(h, sW2[j * 4 + 2], p5);
            p6 = fmaf(h, sW2[j * 4 + 3], p6);
        }
        float R1 = 0.04f * sigmoid_f(0.01f * p0);
        tabC     = 1e-6f * sigmoid_f(0.01f * p1);
        tabR     = R1 * tabC;
        float ox = fmaf(0.79764f, sigmoid_f(0.01f * p5), 0.04236f);
        float oy = fmaf(0.82504f, sigmoid_f(0.01f * p6), 0.023f);

        float up = 4.4167f + oy * (-1.6518f + oy * (1.6225f + oy * (-2.0843f + oy * (3.5146f + oy * (-2.2166f)))));
        up -= 4.0f * __expf(fmaf(109.451f, oy, -100.006f));
        float un = 0.063f + 0.8f * __expf(-75.0f * (ox + 0.001f));
        un -= 0.012f  * tanh_fast(fmaf(ox, 62.5f, -7.9375f));
        un -= 0.0118f * tanh_fast(fmaf(ox, 62.5f, -9.6875f));
        un -= 0.0035f * tanh_fast(fmaf(ox, 50.0f, -11.0f));
        un -= 0.0095f * tanh_fast(fmaf(ox, 76.923076923f, -14.6153846154f));
        un -= 0.0145f * tanh_fast(fmaf(ox, 50.0f, -24.5f));
        un -= 0.08f   * tanh_fast(fmaf(ox, 18.1818181818f, -18.7272727273f));
        tabO = up - un;
    }

    // U1(0): direct eval of theta2 (OCV_U) at soc0 on thread 0
    if (tid == 0) {
        float soc0 = Q * 0.2f;
        float p2 = b2g[2];
#pragma unroll
        for (int j = 0; j < 6; j++) {
            float h = softplus_f(fmaf(soc0, sW10[j], sC1[j]));
            p2 = fmaf(h, W2g[j * 7 + 2], p2);
        }
        float th2 = fmaf(0.75f, sigmoid_f(0.01f * p2), 0.05f);
        sU10 = -th2 - sID[0].x * R0;
    }

    // ---------- phase 1: shfl-table lookup; vOC in regs; (a,b) -> sID; compose ----------
    const float mn = sMn, invD = sInvD;
    float soc = start;
    float A = 1.0f, Bc = 0.0f;
    float vOC[LL];
    float2 cur = sID[tid];
#pragma unroll
    for (int k = 0; k < LL; k++) {
        float2 nxt = (k < LL - 1) ? sID[(k + 1) * NT + tid] : make_float2(I16, 0.0f);
        float Ik = cur.x, dsk = cur.y;

        int idx = __float2int_rn((soc - mn) * invD);
        idx = max(0, min(31, idx));
        float ocv = __shfl_sync(FULL, tabO, idx);
        float C   = __shfl_sync(FULL, tabC, idx);
        float R1C = __shfl_sync(FULL, tabR, idx);

        vOC[k] = fmaf(Ik, R0, ocv);

        float dt = nxt.x - Ik;
        float a  = 1.0f - dt * C;
        float bb = dt * R1C * Ik;
        sID[k * NT + tid] = make_float2(a, bb);
        Bc = fmaf(a, Bc, bb);
        A *= a;

        soc += dsk;
        cur = nxt;
    }

    // ---------- phase 2: block affine scan over (A,B) ----------
#pragma unroll
    for (int o = 1; o < 32; o <<= 1) {
        float Ao = __shfl_up_sync(FULL, A, o);
        float Bo = __shfl_up_sync(FULL, Bc, o);
        if (lane >= o) { Bc = fmaf(A, Bo, Bc); A = A * Ao; }
    }
    float Ax = __shfl_up_sync(FULL, A, 1);
    float Bx = __shfl_up_sync(FULL, Bc, 1);
    if (lane == 0) { Ax = 1.0f; Bx = 0.0f; }
    if (lane == 31) { sWA[wid] = A; sWB[wid] = Bc; }
    __syncthreads();
    if (tid < 32) {
        float wA = (lane < 16) ? sWA[lane] : 1.0f;
        float wB = (lane < 16) ? sWB[lane] : 0.0f;
#pragma unroll
        for (int o = 1; o < 16; o <<= 1) {
            float Ao = __shfl_up_sync(FULL, wA, o);
            float Bo = __shfl_up_sync(FULL, wB, o);
            if (lane >= o) { wB = fmaf(wA, Bo, wB); wA = wA * Ao; }
        }
        float eA = __shfl_up_sync(FULL, wA, 1);
        float eB = __shfl_up_sync(FULL, wB, 1);
        if (lane == 0) { eA = 1.0f; eB = 0.0f; }
        if (lane < 16) { sWA[lane] = eA; sWB[lane] = eB; }
    }
    __syncthreads();
    float wA = sWA[wid], wB = sWB[wid];
    float EA = Ax * wA;
    float EB = fmaf(Ax, wB, Bx);
    float U1 = fmaf(EA, sU10, EB);

    // ---------- phase 3: replay U1 into skewed sV, then coalesced store ----------
#pragma unroll
    for (int k = 0; k < LL; k++) {
        int t = base + k;
        float2 ab = sID[k * NT + tid];
        sV[t + (t >> 4)] = vOC[k] + U1;
        U1 = fmaf(ab.x, U1, ab.y);
    }
    __syncthreads();
    float* ob = out + (size_t)b * TT;
#pragma unroll
    for (int i = 0; i < LL; i++) {
        int idx = tid + i * NT;
        ob[idx] = sV[idx + (idx >> 4)];
    }
}

extern "C" void kernel_launch(void* const* d_in, const int* in_sizes, int n_in,
                              void* d_out, int out_size)
{
    const float* X  = (const float*)d_in[0];
    const float* SC = (const float*)d_in[1];
    const float* W1 = (const float*)d_in[2];
    const float* b1 = (const float*)d_in[3];
    const float* W2 = (const float*)d_in[4];
    const float* b2 = (const float*)d_in[5];
    int B = in_sizes[1] / 2;   // SC is (B,2)
    cudaFuncSetAttribute(voltage_kernel,
                         cudaFuncAttributeMaxDynamicSharedMemorySize, SMEM_BYTES);
    voltage_kernel<<<B, NT, SMEM_BYTES>>>(X, SC, W1, b1, W2, b2, (float*)d_out);
}

// round 9
// speedup vs baseline: 2.9693x; 1.4468x over previous
#include <cuda_runtime.h>
#include <cuda_fp16.h>
#include <cstdint>

// VoltageNet R8: one CTA/batch, 512 thr, 16 steps/thr, 2 CTAs/SM.
// - warp-register SOC table (32 entries/warp), lookup via 2 shuffles (O + packed half2{C,R1C})
// - within-thread affine prefix folded into registers (vB/Aarr): no (a,b) smem round-trip,
//   no serial phase-3 replay
// - sV output-staging buffer aliases sID (64KB total dynamic smem)

#define TT 8192
#define NT 512
#define LL 16
#define FULL 0xFFFFFFFFu
#define SMEM_BYTES (2 * TT * 4)   // float2 sID[TT]; sV aliases (needs 34.8KB < 64KB)

__device__ __forceinline__ float tanh_fast(float x) {
    float y; asm("tanh.approx.f32 %0, %1;" : "=f"(y) : "f"(x)); return y;
}
__device__ __forceinline__ float sigmoid_f(float z) {
    return fmaf(tanh_fast(0.5f * z), 0.5f, 0.5f);
}
__device__ __forceinline__ float softplus_f(float x) {
    return fmaxf(x, 0.0f) + __logf(1.0f + __expf(-fabsf(x)));
}

__global__ __launch_bounds__(NT, 2)
void voltage_kernel(const float* __restrict__ X, const float* __restrict__ SC,
                    const float* __restrict__ W1g, const float* __restrict__ b1g,
                    const float* __restrict__ W2g, const float* __restrict__ b2g,
                    float* __restrict__ out)
{
    extern __shared__ float smem[];
    float2* sID = reinterpret_cast<float2*>(smem);   // [k*NT+tid]: (I, ds)
    float*  sV  = smem;                              // aliases sID (used after it's dead)

    __shared__ float sWS[16], sWA[16], sWB[16], sTr[16], sMnA[16], sMxA[16];
    __shared__ float sW10[6], sW2[24], sB2[4];
    __shared__ float sTmean, sU10, sMn, sInvD, sDelta;

    const int tid  = threadIdx.x;
    const int lane = tid & 31;
    const int wid  = tid >> 5;
    const int b    = blockIdx.x;
    const int base = tid * LL;

    const float Q  = SC[2 * b + 0];
    const float R0 = SC[2 * b + 1];

    // stage MLP constants (W1 soc-col; W2 cols {0,1,5,6}; matching b2)
    if (tid < 6) sW10[tid] = W1g[tid];
    if (tid >= 32 && tid < 56) {
        int i = (tid - 32) >> 2, c = (tid - 32) & 3;
        const int col[4] = {0, 1, 5, 6};
        sW2[tid - 32] = W2g[i * 7 + col[c]];
    }
    if (tid >= 64 && tid < 68) {
        const int col[4] = {0, 1, 5, 6};
        sB2[tid - 64] = b2g[col[tid - 64]];
    }

    // ---------- phase 0: load 16 steps (two 6xfloat4 chunks), stage (I, ds) ----------
    const float invC = 1.0f / 36000.0f;   // 1/(2*3600*QN), QN=5
    float tsum = 0.0f, dsum = 0.0f;
    float rmn = 0.0f, rmx = 0.0f;         // soc excursion relative to thread start
    float pt = 0.0f, pI = 0.0f;
    {
        const float4* px = reinterpret_cast<const float4*>(X + ((size_t)b * TT + base) * 3);
#pragma unroll
        for (int c = 0; c < 2; c++) {
            float4 v[6];
#pragma unroll
            for (int i = 0; i < 6; i++) v[i] = px[c * 6 + i];
            const float* f = reinterpret_cast<const float*>(v);
#pragma unroll
            for (int j = 0; j < 8; j++) {
                int s = c * 8 + j;
                float t = f[3 * j], I = f[3 * j + 1], Te = f[3 * j + 2];
                tsum += Te;
                if (s > 0) {
                    float d = (I + pI) * (t - pt) * invC;
                    dsum += d;
                    rmn = fminf(rmn, dsum);
                    rmx = fmaxf(rmx, dsum);
                    sID[(s - 1) * NT + tid] = make_float2(pI, d);
                }
                pt = t; pI = I;
            }
        }
    }
    float t16 = pt, I16 = pI;             // clamp at end -> ds=0, a=1, b=0
    if (tid < NT - 1) {
        float2 e = *reinterpret_cast<const float2*>(X + ((size_t)b * TT + base + LL) * 3);
        t16 = e.x; I16 = e.y;
    }
    {
        float d = (I16 + pI) * (t16 - pt) * invC;
        dsum += d;
        sID[(LL - 1) * NT + tid] = make_float2(pI, d);
    }

    // ---------- warp pass: scan dsum, reduce tsum + extremes (warp-relative) ----------
    float v = dsum;
#pragma unroll
    for (int o = 1; o < 32; o <<= 1) {
        float n = __shfl_up_sync(FULL, v, o);
        if (lane >= o) v += n;
    }
    float excl = __shfl_up_sync(FULL, v, 1);
    if (lane == 0) excl = 0.0f;
    {
        float wmn = excl + rmn, wmx = excl + rmx;
#pragma unroll
        for (int o = 16; o > 0; o >>= 1) {
            tsum += __shfl_down_sync(FULL, tsum, o);
            wmn = fminf(wmn, __shfl_down_sync(FULL, wmn, o));
            wmx = fmaxf(wmx, __shfl_down_sync(FULL, wmx, o));
        }
        if (lane == 0) { sTr[wid] = tsum; sMnA[wid] = wmn; sMxA[wid] = wmx; }
    }
    if (lane == 31) sWS[wid] = v;
    __syncthreads();

    // ---------- block pass (one warp): warp-sum scan + Tmean + extremes ----------
    if (tid < 32) {
        float w = (lane < 16) ? sWS[lane] : 0.0f;
#pragma unroll
        for (int o = 1; o < 16; o <<= 1) {
            float n = __shfl_up_sync(FULL, w, o);
            if (lane >= o) w += n;
        }
        float e = __shfl_up_sync(FULL, w, 1);
        if (lane == 0) e = 0.0f;
        float ts  = (lane < 16) ? sTr[lane] : 0.0f;
        float bmn = (lane < 16) ? e + sMnA[lane] : 3.4e38f;
        float bmx = (lane < 16) ? e + sMxA[lane] : -3.4e38f;
#pragma unroll
        for (int o = 16; o > 0; o >>= 1) {
            ts  += __shfl_down_sync(FULL, ts, o);
            bmn = fminf(bmn, __shfl_down_sync(FULL, bmn, o));
            bmx = fmaxf(bmx, __shfl_down_sync(FULL, bmx, o));
        }
        if (lane < 16) sWS[lane] = e;
        if (lane == 0) {
            sTmean = ts * (1.0f / TT);
            float mn = fmaf(Q, 0.2f, bmn) - 1e-5f;
            float wdt = (bmx - bmn) + 2e-5f;
            sMn = mn;
            sInvD = 31.0f / wdt;
            sDelta = wdt * (1.0f / 31.0f);
        }
    }
    __syncthreads();

    // ---------- per-warp register table: lane l holds entry l ----------
    float tabO; unsigned tabP;   // tabP = half2{C*1e6, R1C*2.5e7}
    {
        float Tm = sTmean;
        float se = fmaf((float)lane, sDelta, sMn);
        float p0 = sB2[0], p1 = sB2[1], p5 = sB2[2], p6 = sB2[3];
#pragma unroll
        for (int j = 0; j < 6; j++) {
            float c1 = fmaf(R0, W1g[6 + j], fmaf(Tm, W1g[12 + j], b1g[j]));
            float h = softplus_f(fmaf(se, sW10[j], c1));
            p0 = fmaf(h, sW2[j * 4 + 0], p0);
            p1 = fmaf(h, sW2[j * 4 + 1], p1);
            p5 = fmaf(h, sW2[j * 4 + 2], p5);
            p6 = fmaf(h, sW2[j * 4 + 3], p6);
        }
        float R1 = 0.04f * sigmoid_f(0.01f * p0);
        float C  = 1e-6f * sigmoid_f(0.01f * p1);
        __half2 pk = __floats2half2_rn(C * 1e6f, (R1 * C) * 2.5e7f);
        tabP = *reinterpret_cast<unsigned*>(&pk);
        float ox = fmaf(0.79764f, sigmoid_f(0.01f * p5), 0.04236f);
        float oy = fmaf(0.82504f, sigmoid_f(0.01f * p6), 0.023f);

        float up = 4.4167f + oy * (-1.6518f + oy * (1.6225f + oy * (-2.0843f + oy * (3.5146f + oy * (-2.2166f)))));
        up -= 4.0f * __expf(fmaf(109.451f, oy, -100.006f));
        float un = 0.063f + 0.8f * __expf(-75.0f * (ox + 0.001f));
        un -= 0.012f  * tanh_fast(fmaf(ox, 62.5f, -7.9375f));
        un -= 0.0118f * tanh_fast(fmaf(ox, 62.5f, -9.6875f));
        un -= 0.0035f * tanh_fast(fmaf(ox, 50.0f, -11.0f));
        un -= 0.0095f * tanh_fast(fmaf(ox, 76.923076923f, -14.6153846154f));
        un -= 0.0145f * tanh_fast(fmaf(ox, 50.0f, -24.5f));
        un -= 0.08f   * tanh_fast(fmaf(ox, 18.1818181818f, -18.7272727273f));
        tabO = up - un;
    }

    // U1(0): exact theta2 (OCV_U) eval at soc0 on thread 0
    if (tid == 0) {
        float soc0 = Q * 0.2f;
        float Tm = sTmean;
        float p2 = b2g[2];
#pragma unroll
        for (int j = 0; j < 6; j++) {
            float c1 = fmaf(R0, W1g[6 + j], fmaf(Tm, W1g[12 + j], b1g[j]));
            float h = softplus_f(fmaf(soc0, sW10[j], c1));
            p2 = fmaf(h, W2g[j * 7 + 2], p2);
        }
        float th2 = fmaf(0.75f, sigmoid_f(0.01f * p2), 0.05f);
        sU10 = -th2 - sID[0].x * R0;
    }

    // ---------- phase 1: table lookup + register affine-prefix folding ----------
    const float mn = sMn, invD = sInvD;
    const float start = fmaf(Q, 0.2f, sWS[wid] + excl);
    float soc = start;
    float A = 1.0f, Bc = 0.0f;
    float vB[LL], Aarr[LL];
    float2 cur = sID[tid];
#pragma unroll
    for (int k = 0; k < LL; k++) {
        float2 nxt = (k < LL - 1) ? sID[(k + 1) * NT + tid] : make_float2(I16, 0.0f);
        float Ik = cur.x, dsk = cur.y;

        int idx = __float2int_rn((soc - mn) * invD);
        idx = max(0, min(31, idx));
        float ocv = __shfl_sync(FULL, tabO, idx);
        unsigned pu = __shfl_sync(FULL, tabP, idx);
        __half2 ph = *reinterpret_cast<__half2*>(&pu);
        float2 cr = __half22float2(ph);
        float C   = cr.x * 1e-6f;
        float R1C = cr.y * 4e-8f;

        // fold within-thread exclusive prefix: out_k = vB[k] + Aarr[k]*U1start
        vB[k]   = fmaf(Ik, R0, ocv) + Bc;
        Aarr[k] = A;

        float dt = nxt.x - Ik;
        float a  = 1.0f - dt * C;
        float bb = dt * R1C * Ik;
        Bc = fmaf(a, Bc, bb);
        A *= a;

        soc += dsk;
        cur = nxt;
    }

    // ---------- phase 2: block affine scan over thread totals (A, Bc) ----------
#pragma unroll
    for (int o = 1; o < 32; o <<= 1) {
        float Ao = __shfl_up_sync(FULL, A, o);
        float Bo = __shfl_up_sync(FULL, Bc, o);
        if (lane >= o) { Bc = fmaf(A, Bo, Bc); A = A * Ao; }
    }
    float Ax = __shfl_up_sync(FULL, A, 1);
    float Bx = __shfl_up_sync(FULL, Bc, 1);
    if (lane == 0) { Ax = 1.0f; Bx = 0.0f; }
    if (lane == 31) { sWA[wid] = A; sWB[wid] = Bc; }
    __syncthreads();
    if (tid < 32) {
        float wA = (lane < 16) ? sWA[lane] : 1.0f;
        float wB = (lane < 16) ? sWB[lane] : 0.0f;
#pragma unroll
        for (int o = 1; o < 16; o <<= 1) {
            float Ao = __shfl_up_sync(FULL, wA, o);
            float Bo = __shfl_up_sync(FULL, wB, o);
            if (lane >= o) { wB = fmaf(wA, Bo, wB); wA = wA * Ao; }
        }
        float eA = __shfl_up_sync(FULL, wA, 1);
        float eB = __shfl_up_sync(FULL, wB, 1);
        if (lane == 0) { eA = 1.0f; eB = 0.0f; }
        if (lane < 16) { sWA[lane] = eA; sWB[lane] = eB; }
    }
    __syncthreads();   // also fences: sID dead, sV (alias) live from here
    float U1s;
    {
        float wA = sWA[wid], wB = sWB[wid];
        float EA = Ax * wA;
        float EB = fmaf(Ax, wB, Bx);
        U1s = fmaf(EA, sU10, EB);
    }

    // ---------- phase 3: independent finalize into skewed sV, coalesced store ----------
#pragma unroll
    for (int k = 0; k < LL; k++) {
        int t = base + k;
        sV[t + (t >> 4)] = fmaf(Aarr[k], U1s, vB[k]);
    }
    __syncthreads();
    float* ob = out + (size_t)b * TT;
#pragma unroll
    for (int i = 0; i < LL; i++) {
        int idx = tid + i * NT;
        ob[idx] = sV[idx + (idx >> 4)];
    }
}

extern "C" void kernel_launch(void* const* d_in, const int* in_sizes, int n_in,
                              void* d_out, int out_size)
{
    const float* X  = (const float*)d_in[0];
    const float* SC = (const float*)d_in[1];
    const float* W1 = (const float*)d_in[2];
    const float* b1 = (const float*)d_in[3];
    const float* W2 = (const float*)d_in[4];
    const float* b2 = (const float*)d_in[5];
    int B = in_sizes[1] / 2;   // SC is (B,2)
    cudaFuncSetAttribute(voltage_kernel,
                         cudaFuncAttributeMaxDynamicSharedMemorySize, SMEM_BYTES);
    voltage_kernel<<<B, NT, SMEM_BYTES>>>(X, SC, W1, b1, W2, b2, (float*)d_out);
}

// round 10
// speedup vs baseline: 3.3009x; 1.1117x over previous
#include <cuda_runtime.h>
#include <cstdint>

// VoltageNet R9: one CTA/batch, 512 thr, 16 steps/thr, 2 CTAs/SM.
// - X loaded via fully-coalesced LDG.128 -> skewed smem raw chunks (2 x 48KB),
//   extracted into registers (kills the 8x L1 read amplification of R8)
// - per-step state entirely in registers (I[17], r[16]); no (I,ds) smem round-trip
// - warp-register OCV table, 1 shuffle/step; C and R1C block-constant (error ~5e-10)
// - output via skewed sV + LDS.128/STG.128

#define TT 8192
#define NT 512
#define LL 16
#define CH 4096
#define CF (CH * 3)                       // 12288 floats per chunk
#define RAWSLOTS (CF + (CF / 48) * 4)     // skew: +4 floats per 48 -> 13312
#define VSLOTS (TT + (TT / 32) * 4)       // 9216  (fits inside RAWSLOTS)
#define FULL 0xFFFFFFFFu
#define SMEM_BYTES (RAWSLOTS * 4)         // 53248 B

__device__ __forceinline__ float tanh_fast(float x) {
    float y; asm("tanh.approx.f32 %0, %1;" : "=f"(y) : "f"(x)); return y;
}
__device__ __forceinline__ float sigmoid_f(float z) {
    return fmaf(tanh_fast(0.5f * z), 0.5f, 0.5f);
}
__device__ __forceinline__ float softplus_f(float x) {
    return fmaxf(x, 0.0f) + __logf(1.0f + __expf(-fabsf(x)));
}
__device__ __forceinline__ int rawslot(int f) { return f + (f / 48) * 4; }
__device__ __forceinline__ int vslot(int g)  { return g + (g / 32) * 4; }

__global__ __launch_bounds__(NT, 2)
void voltage_kernel(const float* __restrict__ X, const float* __restrict__ SC,
                    const float* __restrict__ W1g, const float* __restrict__ b1g,
                    const float* __restrict__ W2g, const float* __restrict__ b2g,
                    float* __restrict__ out)
{
    extern __shared__ float raw[];        // raw chunk buffer; later aliased as sV

    __shared__ float sWS[16], sWA[16], sWB[16], sTr[16], sMnA[16], sMxA[16];
    __shared__ float sW10[6], sW2[24], sB2[4];
    __shared__ float sTmean, sU10, sMn, sInvD, sDelta;

    const int tid  = threadIdx.x;
    const int lane = tid & 31;
    const int wid  = tid >> 5;
    const int b    = blockIdx.x;
    const int base = tid * LL;

    const float Q  = SC[2 * b + 0];
    const float R0 = SC[2 * b + 1];

    // stage MLP constants (W1 soc-col; W2 cols {0,1,5,6}; matching b2)
    if (tid < 6) sW10[tid] = W1g[tid];
    if (tid >= 32 && tid < 56) {
        int i = (tid - 32) >> 2, c = (tid - 32) & 3;
        const int col[4] = {0, 1, 5, 6};
        sW2[tid - 32] = W2g[i * 7 + col[c]];
    }
    if (tid >= 64 && tid < 68) {
        const int col[4] = {0, 1, 5, 6};
        sB2[tid - 64] = b2g[col[tid - 64]];
    }

    // ---------- phase 0: chunked coalesced load + register extraction ----------
    const float invC = 1.0f / 36000.0f;   // 1/(2*3600*QN), QN=5
    float I[LL + 1], r[LL];
    float tsum = 0.0f, cum = 0.0f, rmn = 0.0f, rmx = 0.0f;
    float pt = 0.0f, dsum = 0.0f;

#pragma unroll
    for (int half = 0; half < 2; half++) {
        // cooperative coalesced load of this chunk
        const float4* src = reinterpret_cast<const float4*>(
            X + (size_t)b * (TT * 3) + half * CF);
        float4 v[6];
#pragma unroll
        for (int j = 0; j < 6; j++) v[j] = src[tid + j * NT];
#pragma unroll
        for (int j = 0; j < 6; j++) {
            int f = 4 * (tid + j * NT);
            *reinterpret_cast<float4*>(&raw[rawslot(f)]) = v[j];
        }
        __syncthreads();

        if ((tid >> 8) == half) {
            int h  = tid & 255;
            int sb = h * 52;              // rawslot(h*48)
#pragma unroll
            for (int s = 0; s < 4; s++) {
                union { float4 q[3]; float f[12]; } u;
                u.q[0] = *reinterpret_cast<float4*>(&raw[sb + s * 12]);
                u.q[1] = *reinterpret_cast<float4*>(&raw[sb + s * 12 + 4]);
                u.q[2] = *reinterpret_cast<float4*>(&raw[sb + s * 12 + 8]);
#pragma unroll
                for (int j = 0; j < 4; j++) {
                    int k = s * 4 + j;
                    float t  = u.f[3 * j];
                    float Ik = u.f[3 * j + 1];
                    tsum += u.f[3 * j + 2];
                    if (k > 0) cum += (Ik + I[k - 1]) * (t - pt) * invC;
                    r[k] = cum;
                    rmn = fminf(rmn, cum);
                    rmx = fmaxf(rmx, cum);
                    I[k] = Ik;
                    pt = t;
                }
            }
            if (h < 255) {                 // boundary step inside this chunk
                float2 bd = *reinterpret_cast<float2*>(&raw[(h + 1) * 52]);
                dsum = cum + (bd.y + I[LL - 1]) * (bd.x - pt) * invC;
                I[LL] = bd.y;
            } else {                       // tid 255: defer; tid 511: clamp
                I[LL] = I[LL - 1];
                dsum = cum;
            }
        }
        __syncthreads();
    }
    // tid 255's boundary = step 4096 = first floats of chunk 1 (still resident)
    if (tid == 255) {
        float2 bd = *reinterpret_cast<float2*>(&raw[0]);
        dsum = cum + (bd.y + I[LL - 1]) * (bd.x - pt) * invC;
        I[LL] = bd.y;
    }

    // ---------- warp pass: scan dsum; reduce tsum + soc extremes ----------
    float v = dsum;
#pragma unroll
    for (int o = 1; o < 32; o <<= 1) {
        float n = __shfl_up_sync(FULL, v, o);
        if (lane >= o) v += n;
    }
    float excl = __shfl_up_sync(FULL, v, 1);
    if (lane == 0) excl = 0.0f;
    {
        float wmn = excl + rmn, wmx = excl + rmx;
#pragma unroll
        for (int o = 16; o > 0; o >>= 1) {
            tsum += __shfl_down_sync(FULL, tsum, o);
            wmn = fminf(wmn, __shfl_down_sync(FULL, wmn, o));
            wmx = fmaxf(wmx, __shfl_down_sync(FULL, wmx, o));
        }
        if (lane == 0) { sTr[wid] = tsum; sMnA[wid] = wmn; sMxA[wid] = wmx; }
    }
    if (lane == 31) sWS[wid] = v;
    __syncthreads();

    // ---------- block pass: warp-sum scan + Tmean + extremes ----------
    if (tid < 32) {
        float w = (lane < 16) ? sWS[lane] : 0.0f;
#pragma unroll
        for (int o = 1; o < 16; o <<= 1) {
            float n = __shfl_up_sync(FULL, w, o);
            if (lane >= o) w += n;
        }
        float e = __shfl_up_sync(FULL, w, 1);
        if (lane == 0) e = 0.0f;
        float ts  = (lane < 16) ? sTr[lane] : 0.0f;
        float bmn = (lane < 16) ? e + sMnA[lane] : 3.4e38f;
        float bmx = (lane < 16) ? e + sMxA[lane] : -3.4e38f;
#pragma unroll
        for (int o = 16; o > 0; o >>= 1) {
            ts  += __shfl_down_sync(FULL, ts, o);
            bmn = fminf(bmn, __shfl_down_sync(FULL, bmn, o));
            bmx = fmaxf(bmx, __shfl_down_sync(FULL, bmx, o));
        }
        if (lane < 16) sWS[lane] = e;
        if (lane == 0) {
            sTmean = ts * (1.0f / TT);
            float mn  = fmaf(Q, 0.2f, bmn) - 1e-5f;
            float wdt = (bmx - bmn) + 2e-5f;
            sMn = mn;
            sInvD = 31.0f / wdt;
            sDelta = wdt * (1.0f / 31.0f);
        }
    }
    __syncthreads();

    // ---------- per-warp register OCV table; block-constant C, R1C ----------
    float tabO, Cc, Rc;
    {
        float Tm = sTmean;
        float se = fmaf((float)lane, sDelta, sMn);
        float p0 = sB2[0], p1 = sB2[1], p5 = sB2[2], p6 = sB2[3];
#pragma unroll
        for (int j = 0; j < 6; j++) {
            float c1 = fmaf(R0, W1g[6 + j], fmaf(Tm, W1g[12 + j], b1g[j]));
            float h = softplus_f(fmaf(se, sW10[j], c1));
            p0 = fmaf(h, sW2[j * 4 + 0], p0);
            p1 = fmaf(h, sW2[j * 4 + 1], p1);
            p5 = fmaf(h, sW2[j * 4 + 2], p5);
            p6 = fmaf(h, sW2[j * 4 + 3], p6);
        }
        float R1 = 0.04f * sigmoid_f(0.01f * p0);
        float C  = 1e-6f * sigmoid_f(0.01f * p1);
        float ox = fmaf(0.79764f, sigmoid_f(0.01f * p5), 0.04236f);
        float oy = fmaf(0.82504f, sigmoid_f(0.01f * p6), 0.023f);

        float up = 4.4167f + oy * (-1.6518f + oy * (1.6225f + oy * (-2.0843f + oy * (3.5146f + oy * (-2.2166f)))));
        up -= 4.0f * __expf(fmaf(109.451f, oy, -100.006f));
        float un = 0.063f + 0.8f * __expf(-75.0f * (ox + 0.001f));
        un -= 0.012f  * tanh_fast(fmaf(ox, 62.5f, -7.9375f));
        un -= 0.0118f * tanh_fast(fmaf(ox, 62.5f, -9.6875f));
        un -= 0.0035f * tanh_fast(fmaf(ox, 50.0f, -11.0f));
        un -= 0.0095f * tanh_fast(fmaf(ox, 76.923076923f, -14.6153846154f));
        un -= 0.0145f * tanh_fast(fmaf(ox, 50.0f, -24.5f));
        un -= 0.08f   * tanh_fast(fmaf(ox, 18.1818181818f, -18.7272727273f));
        tabO = up - un;

        Cc = __shfl_sync(FULL, C, 15);            // mid-range -> block constant
        Rc = __shfl_sync(FULL, R1 * C, 15);
    }

    // U1(0): exact theta2 (OCV_U) eval at soc0 on thread 0 (I[0] in its regs)
    if (tid == 0) {
        float soc0 = Q * 0.2f;
        float Tm = sTmean;
        float p2 = b2g[2];
#pragma unroll
        for (int j = 0; j < 6; j++) {
            float c1 = fmaf(R0, W1g[6 + j], fmaf(Tm, W1g[12 + j], b1g[j]));
            float h = softplus_f(fmaf(soc0, sW10[j], c1));
            p2 = fmaf(h, W2g[j * 7 + 2], p2);
        }
        float th2 = fmaf(0.75f, sigmoid_f(0.01f * p2), 0.05f);
        sU10 = -th2 - I[0] * R0;
    }

    // ---------- phase 1: 1-shuffle lookup + register affine-prefix folding ----------
    const float invD = sInvD;
    const float start = fmaf(Q, 0.2f, sWS[wid] + excl);
    const float s0 = (start - sMn) * invD;
    float A = 1.0f, Bc = 0.0f;
    float vB[LL], Aa[LL];
#pragma unroll
    for (int k = 0; k < LL; k++) {
        int idx = __float2int_rn(fmaf(r[k], invD, s0));
        idx = max(0, min(31, idx));
        float ocv = __shfl_sync(FULL, tabO, idx);

        vB[k] = fmaf(I[k], R0, ocv) + Bc;         // out_k = vB[k] + Aa[k]*U1start
        Aa[k] = A;

        float dI = I[k + 1] - I[k];
        float a  = 1.0f - dI * Cc;
        Bc = fmaf(a, Bc, dI * Rc * I[k]);
        A *= a;
    }

    // ---------- phase 2: block affine scan over thread totals (A, Bc) ----------
#pragma unroll
    for (int o = 1; o < 32; o <<= 1) {
        float Ao = __shfl_up_sync(FULL, A, o);
        float Bo = __shfl_up_sync(FULL, Bc, o);
        if (lane >= o) { Bc = fmaf(A, Bo, Bc); A = A * Ao; }
    }
    float Ax = __shfl_up_sync(FULL, A, 1);
    float Bx = __shfl_up_sync(FULL, Bc, 1);
    if (lane == 0) { Ax = 1.0f; Bx = 0.0f; }
    if (lane == 31) { sWA[wid] = A; sWB[wid] = Bc; }
    __syncthreads();
    if (tid < 32) {
        float wA = (lane < 16) ? sWA[lane] : 1.0f;
        float wB = (lane < 16) ? sWB[lane] : 0.0f;
#pragma unroll
        for (int o = 1; o < 16; o <<= 1) {
            float Ao = __shfl_up_sync(FULL, wA, o);
            float Bo = __shfl_up_sync(FULL, wB, o);
            if (lane >= o) { wB = fmaf(wA, Bo, wB); wA = wA * Ao; }
        }
        float eA = __shfl_up_sync(FULL, wA, 1);
        float eB = __shfl_up_sync(FULL, wB, 1);
        if (lane == 0) { eA = 1.0f; eB = 0.0f; }
        if (lane < 16) { sWA[lane] = eA; sWB[lane] = eB; }
    }
    __syncthreads();   // also fences raw-buffer reuse as sV below
    float U1s;
    {
        float wA = sWA[wid], wB = sWB[wid];
        float EA = Ax * wA;
        float EB = fmaf(Ax, wB, Bx);
        U1s = fmaf(EA, sU10, EB);
    }

    // ---------- phase 3: finalize into skewed sV (aliases raw), 128-bit store ----------
    float* sV = raw;
#pragma unroll
    for (int k = 0; k < LL; k++) {
        int t = base + k;
        sV[vslot(t)] = fmaf(Aa[k], U1s, vB[k]);
    }
    __syncthreads();
    float* ob = out + (size_t)b * TT;
#pragma unroll
    for (int i = 0; i < 4; i++) {
        int g = tid * 4 + i * 2048;
        float4 w = *reinterpret_cast<float4*>(&sV[vslot(g)]);
        *reinterpret_cast<float4*>(ob + g) = w;
    }
}

extern "C" void kernel_launch(void* const* d_in, const int* in_sizes, int n_in,
                              void* d_out, int out_size)
{
    const float* X  = (const float*)d_in[0];
    const float* SC = (const float*)d_in[1];
    const float* W1 = (const float*)d_in[2];
    const float* b1 = (const float*)d_in[3];
    const float* W2 = (const float*)d_in[4];
    const float* b2 = (const float*)d_in[5];
    int B = in_sizes[1] / 2;   // SC is (B,2)
    cudaFuncSetAttribute(voltage_kernel,
                         cudaFuncAttributeMaxDynamicSharedMemorySize, SMEM_BYTES);
    voltage_kernel<<<B, NT, SMEM_BYTES>>>(X, SC, W1, b1, W2, b2, (float*)d_out);
}

// round 11
// speedup vs baseline: 3.4889x; 1.0569x over previous
#include <cuda_runtime.h>
#include <cuda_fp16.h>
#include <cstdint>

// VoltageNet R10: one CTA/batch, 512 thr, 16 steps/thr, 2 CTAs/SM.
// - full-resident X staging (106KB smem): 1 coalesced LDG pass, all threads extract
// - register fit: r[] and (Aa-1)[] packed as half2 (4+4 regs), no spills
// - warp-register OCV table (1 shuffle/step), block-constant C/R1C
// - affine prefix fold; coalesced float4 output via skewed sV (aliases raw)

#define TT 8192
#define NT 512
#define LL 16
#define NF (TT * 3)                        // 24576 floats
#define RAWSLOTS (NF + (NF / 48) * 4)      // skew +4 per 48 -> 26624 floats
#define FULL 0xFFFFFFFFu
#define SMEM_BYTES (RAWSLOTS * 4)          // 106496 B

__device__ __forceinline__ float tanh_fast(float x) {
    float y; asm("tanh.approx.f32 %0, %1;" : "=f"(y) : "f"(x)); return y;
}
__device__ __forceinline__ float sigmoid_f(float z) {
    return fmaf(tanh_fast(0.5f * z), 0.5f, 0.5f);
}
__device__ __forceinline__ float softplus_f(float x) {
    return fmaxf(x, 0.0f) + __logf(1.0f + __expf(-fabsf(x)));
}
__device__ __forceinline__ int rawslot(int f) { return f + (f / 48) * 4; }
__device__ __forceinline__ int vslot(int g)  { return g + (g / 32) * 4; }

__global__ __launch_bounds__(NT, 2)
void voltage_kernel(const float* __restrict__ X, const float* __restrict__ SC,
                    const float* __restrict__ W1g, const float* __restrict__ b1g,
                    const float* __restrict__ W2g, const float* __restrict__ b2g,
                    float* __restrict__ out)
{
    extern __shared__ float raw[];          // full X tile; later aliased as sV

    __shared__ float sWS[16], sWA[16], sWB[16], sTr[16], sMnA[16], sMxA[16];
    __shared__ float sW10[6], sW2[24], sB2[4];
    __shared__ float sTmean, sU10, sMn, sInvD, sDelta;

    const int tid  = threadIdx.x;
    const int lane = tid & 31;
    const int wid  = tid >> 5;
    const int b    = blockIdx.x;
    const int base = tid * LL;

    const float Q  = SC[2 * b + 0];
    const float R0 = SC[2 * b + 1];

    // stage MLP constants (W1 soc-col; W2 cols {0,1,5,6}; matching b2)
    if (tid < 6) sW10[tid] = W1g[tid];
    if (tid >= 32 && tid < 56) {
        int i = (tid - 32) >> 2, c = (tid - 32) & 3;
        const int col[4] = {0, 1, 5, 6};
        sW2[tid - 32] = W2g[i * 7 + col[c]];
    }
    if (tid >= 64 && tid < 68) {
        const int col[4] = {0, 1, 5, 6};
        sB2[tid - 64] = b2g[col[tid - 64]];
    }

    // ---------- phase 0a: one coalesced load pass into skewed smem ----------
    {
        const float4* src = reinterpret_cast<const float4*>(X + (size_t)b * NF);
#pragma unroll
        for (int j = 0; j < 12; j++) {
            float4 v = src[tid + j * NT];
            int f = 4 * (tid + j * NT);
            *reinterpret_cast<float4*>(&raw[rawslot(f)]) = v;
        }
    }
    __syncthreads();

    // ---------- phase 0b: all threads extract their 16 steps ----------
    const float invC = 1.0f / 36000.0f;     // 1/(2*3600*QN), QN=5
    float I[LL + 1];
    __half2 rh[LL / 2];
    float tsum = 0.0f, cum = 0.0f, rmn = 0.0f, rmx = 0.0f;
    float pt = 0.0f, dsum = 0.0f, rlo = 0.0f;
    {
        int sb = tid * 52;                  // rawslot(tid*48); stride 52 = conflict-free
#pragma unroll
        for (int s = 0; s < 4; s++) {
            union { float4 q[3]; float f[12]; } u;
            u.q[0] = *reinterpret_cast<float4*>(&raw[sb + s * 12]);
            u.q[1] = *reinterpret_cast<float4*>(&raw[sb + s * 12 + 4]);
            u.q[2] = *reinterpret_cast<float4*>(&raw[sb + s * 12 + 8]);
#pragma unroll
            for (int j = 0; j < 4; j++) {
                int k = s * 4 + j;
                float t  = u.f[3 * j];
                float Ik = u.f[3 * j + 1];
                tsum += u.f[3 * j + 2];
                if (k > 0) cum += (Ik + I[k - 1]) * (t - pt) * invC;
                rmn = fminf(rmn, cum);
                rmx = fmaxf(rmx, cum);
                if ((k & 1) == 0) rlo = cum;
                else rh[k >> 1] = __floats2half2_rn(rlo, cum);
                I[k] = Ik;
                pt = t;
            }
        }
        if (tid < NT - 1) {                 // boundary step (resident for all)
            float2 bd = *reinterpret_cast<float2*>(&raw[(tid + 1) * 52]);
            dsum = cum + (bd.y + I[LL - 1]) * (bd.x - pt) * invC;
            I[LL] = bd.y;
        } else {                            // clamp -> ds=0, a=1, b=0
            I[LL] = I[LL - 1];
            dsum = cum;
        }
    }

    // ---------- warp pass: scan dsum; reduce tsum + soc extremes ----------
    float v = dsum;
#pragma unroll
    for (int o = 1; o < 32; o <<= 1) {
        float n = __shfl_up_sync(FULL, v, o);
        if (lane >= o) v += n;
    }
    float excl = __shfl_up_sync(FULL, v, 1);
    if (lane == 0) excl = 0.0f;
    {
        float wmn = excl + rmn, wmx = excl + rmx;
#pragma unroll
        for (int o = 16; o > 0; o >>= 1) {
            tsum += __shfl_down_sync(FULL, tsum, o);
            wmn = fminf(wmn, __shfl_down_sync(FULL, wmn, o));
            wmx = fmaxf(wmx, __shfl_down_sync(FULL, wmx, o));
        }
        if (lane == 0) { sTr[wid] = tsum; sMnA[wid] = wmn; sMxA[wid] = wmx; }
    }
    if (lane == 31) sWS[wid] = v;
    __syncthreads();

    // ---------- block pass: warp-sum scan + Tmean + extremes ----------
    if (tid < 32) {
        float w = (lane < 16) ? sWS[lane] : 0.0f;
#pragma unroll
        for (int o = 1; o < 16; o <<= 1) {
            float n = __shfl_up_sync(FULL, w, o);
            if (lane >= o) w += n;
        }
        float e = __shfl_up_sync(FULL, w, 1);
        if (lane == 0) e = 0.0f;
        float ts  = (lane < 16) ? sTr[lane] : 0.0f;
        float bmn = (lane < 16) ? e + sMnA[lane] : 3.4e38f;
        float bmx = (lane < 16) ? e + sMxA[lane] : -3.4e38f;
#pragma unroll
        for (int o = 16; o > 0; o >>= 1) {
            ts  += __shfl_down_sync(FULL, ts, o);
            bmn = fminf(bmn, __shfl_down_sync(FULL, bmn, o));
            bmx = fmaxf(bmx, __shfl_down_sync(FULL, bmx, o));
        }
        if (lane < 16) sWS[lane] = e;
        if (lane == 0) {
            sTmean = ts * (1.0f / TT);
            float mn  = fmaf(Q, 0.2f, bmn) - 1e-5f;
            float wdt = (bmx - bmn) + 2e-5f;
            sMn = mn;
            sInvD = 31.0f / wdt;
            sDelta = wdt * (1.0f / 31.0f);
        }
    }
    __syncthreads();

    // ---------- per-warp register OCV table; block-constant C, R1C ----------
    float tabO, Cc, Rc;
    {
        float Tm = sTmean;
        float se = fmaf((float)lane, sDelta, sMn);
        float p0 = sB2[0], p1 = sB2[1], p5 = sB2[2], p6 = sB2[3];
#pragma unroll
        for (int j = 0; j < 6; j++) {
            float c1 = fmaf(R0, W1g[6 + j], fmaf(Tm, W1g[12 + j], b1g[j]));
            float h = softplus_f(fmaf(se, sW10[j], c1));
            p0 = fmaf(h, sW2[j * 4 + 0], p0);
            p1 = fmaf(h, sW2[j * 4 + 1], p1);
            p5 = fmaf(h, sW2[j * 4 + 2], p5);
            p6 = fmaf(h, sW2[j * 4 + 3], p6);
        }
        float R1 = 0.04f * sigmoid_f(0.01f * p0);
        float C  = 1e-6f * sigmoid_f(0.01f * p1);
        float ox = fmaf(0.79764f, sigmoid_f(0.01f * p5), 0.04236f);
        float oy = fmaf(0.82504f, sigmoid_f(0.01f * p6), 0.023f);

        float up = 4.4167f + oy * (-1.6518f + oy * (1.6225f + oy * (-2.0843f + oy * (3.5146f + oy * (-2.2166f)))));
        up -= 4.0f * __expf(fmaf(109.451f, oy, -100.006f));
        float un = 0.063f + 0.8f * __expf(-75.0f * (ox + 0.001f));
        un -= 0.012f  * tanh_fast(fmaf(ox, 62.5f, -7.9375f));
        un -= 0.0118f * tanh_fast(fmaf(ox, 62.5f, -9.6875f));
        un -= 0.0035f * tanh_fast(fmaf(ox, 50.0f, -11.0f));
        un -= 0.0095f * tanh_fast(fmaf(ox, 76.923076923f, -14.6153846154f));
        un -= 0.0145f * tanh_fast(fmaf(ox, 50.0f, -24.5f));
        un -= 0.08f   * tanh_fast(fmaf(ox, 18.1818181818f, -18.7272727273f));
        tabO = up - un;

        Cc = __shfl_sync(FULL, C, 15);      // mid-range -> block constant
        Rc = __shfl_sync(FULL, R1 * C, 15);
    }

    // U1(0): exact theta2 (OCV_U) eval at soc0 on thread 0
    if (tid == 0) {
        float soc0 = Q * 0.2f;
        float Tm = sTmean;
        float p2 = b2g[2];
#pragma unroll
        for (int j = 0; j < 6; j++) {
            float c1 = fmaf(R0, W1g[6 + j], fmaf(Tm, W1g[12 + j], b1g[j]));
            float h = softplus_f(fmaf(soc0, sW10[j], c1));
            p2 = fmaf(h, W2g[j * 7 + 2], p2);
        }
        float th2 = fmaf(0.75f, sigmoid_f(0.01f * p2), 0.05f);
        sU10 = -th2 - I[0] * R0;
    }

    // ---------- phase 1: 1-shuffle lookup + affine fold (Aa-1 packed half2) ----------
    const float invD = sInvD;
    const float start = fmaf(Q, 0.2f, sWS[wid] + excl);
    const float s0 = (start - sMn) * invD;
    float A = 1.0f, Bc = 0.0f;
    float vB[LL];
    __half2 ah[LL / 2];
    float alo = 0.0f;
#pragma unroll
    for (int k = 0; k < LL; k++) {
        float2 rr = __half22float2(rh[k >> 1]);
        float rk = (k & 1) ? rr.y : rr.x;
        int idx = __float2int_rn(fmaf(rk, invD, s0));
        idx = max(0, min(31, idx));
        float ocv = __shfl_sync(FULL, tabO, idx);

        vB[k] = fmaf(I[k], R0, ocv) + Bc;   // out_k = vB[k] + Aa[k]*U1s
        float am1 = A - 1.0f;               // |Aa-1| <= ~1e-4 -> half-safe
        if ((k & 1) == 0) alo = am1;
        else ah[k >> 1] = __floats2half2_rn(alo, am1);

        float dI = I[k + 1] - I[k];
        float a  = 1.0f - dI * Cc;
        Bc = fmaf(a, Bc, dI * Rc * I[k]);
        A *= a;
    }

    // ---------- phase 2: block affine scan over thread totals (A, Bc) ----------
#pragma unroll
    for (int o = 1; o < 32; o <<= 1) {
        float Ao = __shfl_up_sync(FULL, A, o);
        float Bo = __shfl_up_sync(FULL, Bc, o);
        if (lane >= o) { Bc = fmaf(A, Bo, Bc); A = A * Ao; }
    }
    float Ax = __shfl_up_sync(FULL, A, 1);
    float Bx = __shfl_up_sync(FULL, Bc, 1);
    if (lane == 0) { Ax = 1.0f; Bx = 0.0f; }
    if (lane == 31) { sWA[wid] = A; sWB[wid] = Bc; }
    __syncthreads();
    if (tid < 32) {
        float wA = (lane < 16) ? sWA[lane] : 1.0f;
        float wB = (lane < 16) ? sWB[lane] : 0.0f;
#pragma unroll
        for (int o = 1; o < 16; o <<= 1) {
            float Ao = __shfl_up_sync(FULL, wA, o);
            float Bo = __shfl_up_sync(FULL, wB, o);
            if (lane >= o) { wB = fmaf(wA, Bo, wB); wA = wA * Ao; }
        }
        float eA = __shfl_up_sync(FULL, wA, 1);
        float eB = __shfl_up_sync(FULL, wB, 1);
        if (lane == 0) { eA = 1.0f; eB = 0.0f; }
        if (lane < 16) { sWA[lane] = eA; sWB[lane] = eB; }
    }
    __syncthreads();   // also fences raw-buffer reuse as sV below
    float U1s;
    {
        float wA = sWA[wid], wB = sWB[wid];
        float EA = Ax * wA;
        float EB = fmaf(Ax, wB, Bx);
        U1s = fmaf(EA, sU10, EB);
    }

    // ---------- phase 3: finalize into skewed sV (aliases raw), float4 store ----------
    float* sV = raw;
#pragma unroll
    for (int k = 0; k < LL; k++) {
        float2 aa = __half22float2(ah[k >> 1]);
        float am1 = (k & 1) ? aa.y : aa.x;
        int t = base + k;
        sV[vslot(t)] = fmaf(am1, U1s, vB[k] + U1s);
    }
    __syncthreads();
    float* ob = out + (size_t)b * TT;
#pragma unroll
    for (int i = 0; i < 4; i++) {
        int g = tid * 4 + i * 2048;
        float4 w = *reinterpret_cast<float4*>(&sV[vslot(g)]);
        *reinterpret_cast<float4*>(ob + g) = w;
    }
}

extern "C" void kernel_launch(void* const* d_in, const int* in_sizes, int n_in,
                              void* d_out, int out_size)
{
    const float* X  = (const float*)d_in[0];
    const float* SC = (const float*)d_in[1];
    const float* W1 = (const float*)d_in[2];
    const float* b1 = (const float*)d_in[3];
    const float* W2 = (const float*)d_in[4];
    const float* b2 = (const float*)d_in[5];
    int B = in_sizes[1] / 2;   // SC is (B,2)
    cudaFuncSetAttribute(voltage_kernel,
                         cudaFuncAttributeMaxDynamicSharedMemorySize, SMEM_BYTES);
    voltage_kernel<<<B, NT, SMEM_BYTES>>>(X, SC, W1, b1, W2, b2, (float*)d_out);
}

// round 13
// speedup vs baseline: 3.8061x; 1.0909x over previous
#include <cuda_runtime.h>
#include <cuda_fp16.h>
#include <cstdint>

// VoltageNet R12 (= R11 with alignment-safe output skew):
// Affine scan removed analytically:
//   A_k = prod(1 - dI*C) = exp(-C*(I_k - I_0)) ~= 1 - C*(I_k - I_0)   (telescoped)
//   B_k ~= R1C * S_k,  S_k = prefix sum of dI*I  (discount = 1 +- 1e-5)
// -> out_k = OCV(soc_k) + I_k*(R0 - U10*C) + R1C*S_k + const   (pointwise!)
// Two prefix sums (soc, S) merged into ONE scan pass. 2 block barriers total.
// Warp-local staging regions; output skew vslot (4 per 32) keeps float4 alignment.

#define TT 8192
#define NT 512
#define LL 16
#define REG 1664                     // floats per warp region (32 lanes * 52)
#define FULL 0xFFFFFFFFu
#define SMEM_BYTES (16 * REG * 4)    // 106496 B

__device__ __forceinline__ float tanh_fast(float x) {
    float y; asm("tanh.approx.f32 %0, %1;" : "=f"(y) : "f"(x)); return y;
}
__device__ __forceinline__ float sigmoid_f(float z) {
    return fmaf(tanh_fast(0.5f * z), 0.5f, 0.5f);
}
__device__ __forceinline__ float softplus_f(float x) {
    return fmaxf(x, 0.0f) + __logf(1.0f + __expf(-fabsf(x)));
}
__device__ __forceinline__ int rawslot(int f) { return f + (f / 48) * 4; }
__device__ __forceinline__ int vslot(int g)   { return g + (g >> 5) * 4; }  // 16B-safe

__global__ __launch_bounds__(NT, 2)
void voltage_kernel(const float* __restrict__ X, const float* __restrict__ SC,
                    const float* __restrict__ W1g, const float* __restrict__ b1g,
                    const float* __restrict__ W2g, const float* __restrict__ b2g,
                    float* __restrict__ out)
{
    extern __shared__ float raw[];   // 16 warp regions of REG floats

    __shared__ float sWS[16], sPS[16], sWSe[16], sPSe[16];
    __shared__ float sTr[16], sMnA[16], sMxA[16];
    __shared__ float sW10[6], sW2[30], sB2[5];
    __shared__ float sTmean, sMn, sInvD, sDelta, sI0;

    const int tid  = threadIdx.x;
    const int lane = tid & 31;
    const int wid  = tid >> 5;
    const int b    = blockIdx.x;

    const float Q  = SC[2 * b + 0];
    const float R0 = SC[2 * b + 1];

    // stage MLP constants (W1 soc-col; W2 cols {0,1,2,5,6}; matching b2)
    if (tid < 6) sW10[tid] = W1g[tid];
    if (tid >= 32 && tid < 62) {
        int i = (tid - 32) / 5, c = (tid - 32) % 5;
        const int col[5] = {0, 1, 2, 5, 6};
        sW2[tid - 32] = W2g[i * 7 + col[c]];
    }
    if (tid >= 64 && tid < 69) {
        const int col[5] = {0, 1, 2, 5, 6};
        sB2[tid - 64] = b2g[col[tid - 64]];
    }

    // ---------- phase 0a: warp-local coalesced load of own 512-step segment ----------
    const float* gbf = X + (size_t)b * (TT * 3) + wid * 1536;
    {
        const float4* gb4 = reinterpret_cast<const float4*>(gbf);
        float* rg = raw + wid * REG;
#pragma unroll
        for (int j = 0; j < 12; j++) {
            float4 v = gb4[lane + 32 * j];
            *reinterpret_cast<float4*>(&rg[rawslot(4 * (lane + 32 * j))]) = v;
        }
        if (lane == 0 && wid < 15) {     // boundary (t,I) of next segment into tail
            float2 bd = *reinterpret_cast<const float2*>(gbf + 1536);
            rg[1660] = bd.x; rg[1661] = bd.y;
        }
    }
    __syncwarp();

    // ---------- phase 0b: extract own 16 steps; dual prefixes (soc cum, S cum) ----------
    const float invC = 1.0f / 36000.0f;  // 1/(2*3600*QN), QN=5
    float I[LL + 1];
    __half2 rh[LL / 2], sh[LL / 2];
    float tsum = 0.0f, cum = 0.0f, scum = 0.0f;
    float rmn = 0.0f, rmx = 0.0f, pt = 0.0f;
    float rlo = 0.0f, slo = 0.0f;
    {
        const int sb0 = wid * REG + lane * 52;
#pragma unroll
        for (int s = 0; s < 4; s++) {
            union { float4 q[3]; float f[12]; } u;
            u.q[0] = *reinterpret_cast<float4*>(&raw[sb0 + s * 12]);
            u.q[1] = *reinterpret_cast<float4*>(&raw[sb0 + s * 12 + 4]);
            u.q[2] = *reinterpret_cast<float4*>(&raw[sb0 + s * 12 + 8]);
#pragma unroll
            for (int j = 0; j < 4; j++) {
                int k = s * 4 + j;
                float t  = u.f[3 * j];
                float Ik = u.f[3 * j + 1];
                tsum += u.f[3 * j + 2];
                if (k > 0) {
                    cum  += (Ik + I[k - 1]) * (t - pt) * invC;
                    scum += (Ik - I[k - 1]) * I[k - 1];    // p_{k-1} -> exclusive S
                }
                rmn = fminf(rmn, cum);
                rmx = fmaxf(rmx, cum);
                if ((k & 1) == 0) { rlo = cum; slo = scum; }
                else { rh[k >> 1] = __floats2half2_rn(rlo, cum);
                       sh[k >> 1] = __floats2half2_rn(slo, scum); }
                I[k] = Ik;
                pt = t;
            }
        }
    }
    float dsum, ptot;
    {
        float tb, Ib;
        if (lane < 31) {
            float2 bd = *reinterpret_cast<float2*>(&raw[wid * REG + (lane + 1) * 52]);
            tb = bd.x; Ib = bd.y;
        } else if (wid < 15) {
            float2 bd = *reinterpret_cast<float2*>(&raw[wid * REG + 1660]);
            tb = bd.x; Ib = bd.y;
        } else {                          // tid 511: clamp -> ds=0, p=0
            tb = pt; Ib = I[LL - 1];
        }
        I[LL] = Ib;
        dsum = cum + (Ib + I[LL - 1]) * (tb - pt) * invC;
        ptot = scum + (Ib - I[LL - 1]) * I[LL - 1];
    }
    if (tid == 0) sI0 = I[0];

    // ---------- warp pass: dual inclusive scan (dsum, ptot); reduce tsum/mn/mx ----------
    float v = dsum, pv = ptot;
#pragma unroll
    for (int o = 1; o < 32; o <<= 1) {
        float n  = __shfl_up_sync(FULL, v, o);
        float np = __shfl_up_sync(FULL, pv, o);
        if (lane >= o) { v += n; pv += np; }
    }
    float excl  = __shfl_up_sync(FULL, v, 1);
    float pexcl = __shfl_up_sync(FULL, pv, 1);
    if (lane == 0) { excl = 0.0f; pexcl = 0.0f; }
    {
        float wmn = excl + rmn, wmx = excl + rmx;
#pragma unroll
        for (int o = 16; o > 0; o >>= 1) {
            tsum += __shfl_down_sync(FULL, tsum, o);
            wmn = fminf(wmn, __shfl_down_sync(FULL, wmn, o));
            wmx = fmaxf(wmx, __shfl_down_sync(FULL, wmx, o));
        }
        if (lane == 0) { sTr[wid] = tsum; sMnA[wid] = wmn; sMxA[wid] = wmx; }
    }
    if (lane == 31) { sWS[wid] = v; sPS[wid] = pv; }
    __syncthreads();                                  // barrier #1

    // ---------- block pass (one warp): dual scan of warp totals + Tmean + extremes ----------
    if (tid < 32) {
        float w  = (lane < 16) ? sWS[lane] : 0.0f;
        float pw = (lane < 16) ? sPS[lane] : 0.0f;
#pragma unroll
        for (int o = 1; o < 16; o <<= 1) {
            float n  = __shfl_up_sync(FULL, w, o);
            float np = __shfl_up_sync(FULL, pw, o);
            if (lane >= o) { w += n; pw += np; }
        }
        float e  = __shfl_up_sync(FULL, w, 1);
        float ep = __shfl_up_sync(FULL, pw, 1);
        if (lane == 0) { e = 0.0f; ep = 0.0f; }
        float ts  = (lane < 16) ? sTr[lane] : 0.0f;
        float bmn = (lane < 16) ? e + sMnA[lane] : 3.4e38f;
        float bmx = (lane < 16) ? e + sMxA[lane] : -3.4e38f;
#pragma unroll
        for (int o = 16; o > 0; o >>= 1) {
            ts  += __shfl_down_sync(FULL, ts, o);
            bmn = fminf(bmn, __shfl_down_sync(FULL, bmn, o));
            bmx = fmaxf(bmx, __shfl_down_sync(FULL, bmx, o));
        }
        if (lane < 16) { sWSe[lane] = e; sPSe[lane] = ep; }
        if (lane == 0) {
            sTmean = ts * (1.0f / TT);
            float mn  = fmaf(Q, 0.2f, bmn) - 1e-5f;
            float wdt = (bmx - bmn) + 2e-5f;
            sMn = mn;
            sInvD  = 31.0f / wdt;
            sDelta = wdt * (1.0f / 31.0f);
        }
    }
    __syncthreads();                                  // barrier #2

    // ---------- per-warp register table (OCV, th2); block constants C, R1C ----------
    float tabO, tabT, Cc, Rc;
    {
        float Tm = sTmean;
        float se = fmaf((float)lane, sDelta, sMn);
        float p0 = sB2[0], p1 = sB2[1], p2 = sB2[2], p5 = sB2[3], p6 = sB2[4];
#pragma unroll
        for (int j = 0; j < 6; j++) {
            float c1 = fmaf(R0, W1g[6 + j], fmaf(Tm, W1g[12 + j], b1g[j]));
            float h = softplus_f(fmaf(se, sW10[j], c1));
            p0 = fmaf(h, sW2[j * 5 + 0], p0);
            p1 = fmaf(h, sW2[j * 5 + 1], p1);
            p2 = fmaf(h, sW2[j * 5 + 2], p2);
            p5 = fmaf(h, sW2[j * 5 + 3], p5);
            p6 = fmaf(h, sW2[j * 5 + 4], p6);
        }
        float R1 = 0.04f * sigmoid_f(0.01f * p0);
        float C  = 1e-6f * sigmoid_f(0.01f * p1);
        tabT = fmaf(0.75f, sigmoid_f(0.01f * p2), 0.05f);
        float ox = fmaf(0.79764f, sigmoid_f(0.01f * p5), 0.04236f);
        float oy = fmaf(0.82504f, sigmoid_f(0.01f * p6), 0.023f);

        float up = 4.4167f + oy * (-1.6518f + oy * (1.6225f + oy * (-2.0843f + oy * (3.5146f + oy * (-2.2166f)))));
        up -= 4.0f * __expf(fmaf(109.451f, oy, -100.006f));
        float un = 0.063f + 0.8f * __expf(-75.0f * (ox + 0.001f));
        un -= 0.012f  * tanh_fast(fmaf(ox, 62.5f, -7.9375f));
        un -= 0.0118f * tanh_fast(fmaf(ox, 62.5f, -9.6875f));
        un -= 0.0035f * tanh_fast(fmaf(ox, 50.0f, -11.0f));
        un -= 0.0095f * tanh_fast(fmaf(ox, 76.923076923f, -14.6153846154f));
        un -= 0.0145f * tanh_fast(fmaf(ox, 50.0f, -24.5f));
        un -= 0.08f   * tanh_fast(fmaf(ox, 18.1818181818f, -18.7272727273f));
        tabO = up - un;

        Cc = __shfl_sync(FULL, C, 15);                // mid-range -> block constant
        Rc = __shfl_sync(FULL, R1 * C, 15);
    }

    // ---------- pointwise finalize ----------
    const float mn = sMn, invD = sInvD;
    const float I0 = sI0;
    float U10;
    {   // th2 at soc0 from table (soc0 = Q/QN = thread 0's start, inside range)
        int i0 = __float2int_rn((Q * 0.2f - mn) * invD);
        i0 = max(0, min(31, i0));
        float th2 = __shfl_sync(FULL, tabT, i0);
        U10 = -th2 - I0 * R0;
    }
    const float start = fmaf(Q, 0.2f, sWSe[wid] + excl);
    const float s0 = (start - mn) * invD;
    const float Sbase = sPSe[wid] + pexcl;
    const float uc = U10 * Cc;                 // U1 = U10 - uc*(I-I0) + Rc*(Sbase+s)
    const float cI = R0 - uc;                  // coefficient of I_k
    const float c0 = U10 + uc * I0 + Rc * Sbase;
    float* rg = raw + wid * REG;
#pragma unroll
    for (int k = 0; k < LL; k++) {
        float2 rr = __half22float2(rh[k >> 1]);
        float rk = (k & 1) ? rr.y : rr.x;
        float2 ss = __half22float2(sh[k >> 1]);
        float sk = (k & 1) ? ss.y : ss.x;
        int idx = __float2int_rn(fmaf(rk, invD, s0));
        idx = max(0, min(31, idx));
        float ocv = __shfl_sync(FULL, tabO, idx);
        rg[vslot(lane * LL + k)] = fmaf(I[k], cI, fmaf(Rc, sk, c0)) + ocv;
    }
    __syncwarp();

    // ---------- warp-local transpose out: LDS.128 + STG.128, fully coalesced ----------
    float* ob = out + (size_t)b * TT + wid * 512;
#pragma unroll
    for (int j = 0; j < 4; j++) {
        int x = 4 * lane + 128 * j;
        float4 w = *reinterpret_cast<float4*>(&rg[vslot(x)]);
        *reinterpret_cast<float4*>(ob + x) = w;
    }
}

extern "C" void kernel_launch(void* const* d_in, const int* in_sizes, int n_in,
                              void* d_out, int out_size)
{
    const float* X  = (const float*)d_in[0];
    const float* SC = (const float*)d_in[1];
    const float* W1 = (const float*)d_in[2];
    const float* b1 = (const float*)d_in[3];
    const float* W2 = (const float*)d_in[4];
    const float* b2 = (const float*)d_in[5];
    int B = in_sizes[1] / 2;   // SC is (B,2)
    cudaFuncSetAttribute(voltage_kernel,
                         cudaFuncAttributeMaxDynamicSharedMemorySize, SMEM_BYTES);
    voltage_kernel<<<B, NT, SMEM_BYTES>>>(X, SC, W1, b1, W2, b2, (float*)d_out);
}

// round 14
// speedup vs baseline: 3.9006x; 1.0248x over previous
#include <cuda_runtime.h>
#include <cuda_fp16.h>
#include <cstdint>

// VoltageNet R13 (= R12 + per-thread OCV linearization, no in-loop shuffles):
//   out_k = OCV(soc_k) + I_k*(R0 - U10*C) + R1C*S_k + const      (pointwise)
//   OCV(soc_k) ~= O0 + slopeD * r_k   (thread-local linearization from warp table)
// Dual prefix sums (soc, S) in ONE scan pass; 2 block barriers; warp-local staging.

#define TT 8192
#define NT 512
#define LL 16
#define REG 1664                     // floats per warp region (32 lanes * 52)
#define FULL 0xFFFFFFFFu
#define SMEM_BYTES (16 * REG * 4)    // 106496 B

__device__ __forceinline__ float tanh_fast(float x) {
    float y; asm("tanh.approx.f32 %0, %1;" : "=f"(y) : "f"(x)); return y;
}
__device__ __forceinline__ float sigmoid_f(float z) {
    return fmaf(tanh_fast(0.5f * z), 0.5f, 0.5f);
}
__device__ __forceinline__ float softplus_f(float x) {
    return fmaxf(x, 0.0f) + __logf(1.0f + __expf(-fabsf(x)));
}
__device__ __forceinline__ int rawslot(int f) { return f + (f / 48) * 4; }
__device__ __forceinline__ int vslot(int g)   { return g + (g >> 5) * 4; }  // 16B-safe

__global__ __launch_bounds__(NT, 2)
void voltage_kernel(const float* __restrict__ X, const float* __restrict__ SC,
                    const float* __restrict__ W1g, const float* __restrict__ b1g,
                    const float* __restrict__ W2g, const float* __restrict__ b2g,
                    float* __restrict__ out)
{
    extern __shared__ float raw[];   // 16 warp regions of REG floats

    __shared__ float sWS[16], sPS[16], sWSe[16], sPSe[16];
    __shared__ float sTr[16], sMnA[16], sMxA[16];
    __shared__ float sW10[6], sW2[30], sB2[5];
    __shared__ float sTmean, sMn, sInvD, sDelta, sI0;

    const int tid  = threadIdx.x;
    const int lane = tid & 31;
    const int wid  = tid >> 5;
    const int b    = blockIdx.x;

    const float Q  = SC[2 * b + 0];
    const float R0 = SC[2 * b + 1];

    // stage MLP constants (W1 soc-col; W2 cols {0,1,2,5,6}; matching b2)
    if (tid < 6) sW10[tid] = W1g[tid];
    if (tid >= 32 && tid < 62) {
        int i = (tid - 32) / 5, c = (tid - 32) % 5;
        const int col[5] = {0, 1, 2, 5, 6};
        sW2[tid - 32] = W2g[i * 7 + col[c]];
    }
    if (tid >= 64 && tid < 69) {
        const int col[5] = {0, 1, 2, 5, 6};
        sB2[tid - 64] = b2g[col[tid - 64]];
    }

    // ---------- phase 0a: warp-local coalesced load of own 512-step segment ----------
    const float* gbf = X + (size_t)b * (TT * 3) + wid * 1536;
    {
        const float4* gb4 = reinterpret_cast<const float4*>(gbf);
        float* rg = raw + wid * REG;
#pragma unroll
        for (int j = 0; j < 12; j++) {
            float4 v = gb4[lane + 32 * j];
            *reinterpret_cast<float4*>(&rg[rawslot(4 * (lane + 32 * j))]) = v;
        }
        if (lane == 0 && wid < 15) {     // boundary (t,I) of next segment into tail
            float2 bd = *reinterpret_cast<const float2*>(gbf + 1536);
            rg[1660] = bd.x; rg[1661] = bd.y;
        }
    }
    __syncwarp();

    // ---------- phase 0b: extract own 16 steps; dual prefixes (soc cum, S cum) ----------
    const float invC = 1.0f / 36000.0f;  // 1/(2*3600*QN), QN=5
    float I[LL + 1];
    __half2 rh[LL / 2], sh[LL / 2];
    float tsum = 0.0f, cum = 0.0f, scum = 0.0f;
    float rmn = 0.0f, rmx = 0.0f, pt = 0.0f;
    float rlo = 0.0f, slo = 0.0f;
    {
        const int sb0 = wid * REG + lane * 52;
#pragma unroll
        for (int s = 0; s < 4; s++) {
            union { float4 q[3]; float f[12]; } u;
            u.q[0] = *reinterpret_cast<float4*>(&raw[sb0 + s * 12]);
            u.q[1] = *reinterpret_cast<float4*>(&raw[sb0 + s * 12 + 4]);
            u.q[2] = *reinterpret_cast<float4*>(&raw[sb0 + s * 12 + 8]);
#pragma unroll
            for (int j = 0; j < 4; j++) {
                int k = s * 4 + j;
                float t  = u.f[3 * j];
                float Ik = u.f[3 * j + 1];
                tsum += u.f[3 * j + 2];
                if (k > 0) {
                    cum  += (Ik + I[k - 1]) * (t - pt) * invC;
                    scum += (Ik - I[k - 1]) * I[k - 1];    // p_{k-1} -> exclusive S
                }
                rmn = fminf(rmn, cum);
                rmx = fmaxf(rmx, cum);
                if ((k & 1) == 0) { rlo = cum; slo = scum; }
                else { rh[k >> 1] = __floats2half2_rn(rlo, cum);
                       sh[k >> 1] = __floats2half2_rn(slo, scum); }
                I[k] = Ik;
                pt = t;
            }
        }
    }
    float dsum, ptot;
    {
        float tb, Ib;
        if (lane < 31) {
            float2 bd = *reinterpret_cast<float2*>(&raw[wid * REG + (lane + 1) * 52]);
            tb = bd.x; Ib = bd.y;
        } else if (wid < 15) {
            float2 bd = *reinterpret_cast<float2*>(&raw[wid * REG + 1660]);
            tb = bd.x; Ib = bd.y;
        } else {                          // tid 511: clamp -> ds=0, p=0
            tb = pt; Ib = I[LL - 1];
        }
        I[LL] = Ib;
        dsum = cum + (Ib + I[LL - 1]) * (tb - pt) * invC;
        ptot = scum + (Ib - I[LL - 1]) * I[LL - 1];
    }
    if (tid == 0) sI0 = I[0];

    // ---------- warp pass: dual inclusive scan (dsum, ptot); reduce tsum/mn/mx ----------
    float v = dsum, pv = ptot;
#pragma unroll
    for (int o = 1; o < 32; o <<= 1) {
        float n  = __shfl_up_sync(FULL, v, o);
        float np = __shfl_up_sync(FULL, pv, o);
        if (lane >= o) { v += n; pv += np; }
    }
    float excl  = __shfl_up_sync(FULL, v, 1);
    float pexcl = __shfl_up_sync(FULL, pv, 1);
    if (lane == 0) { excl = 0.0f; pexcl = 0.0f; }
    {
        float wmn = excl + rmn, wmx = excl + rmx;
#pragma unroll
        for (int o = 16; o > 0; o >>= 1) {
            tsum += __shfl_down_sync(FULL, tsum, o);
            wmn = fminf(wmn, __shfl_down_sync(FULL, wmn, o));
            wmx = fmaxf(wmx, __shfl_down_sync(FULL, wmx, o));
        }
        if (lane == 0) { sTr[wid] = tsum; sMnA[wid] = wmn; sMxA[wid] = wmx; }
    }
    if (lane == 31) { sWS[wid] = v; sPS[wid] = pv; }
    __syncthreads();                                  // barrier #1

    // ---------- block pass (one warp): dual scan of warp totals + Tmean + extremes ----------
    if (tid < 32) {
        float w  = (lane < 16) ? sWS[lane] : 0.0f;
        float pw = (lane < 16) ? sPS[lane] : 0.0f;
#pragma unroll
        for (int o = 1; o < 16; o <<= 1) {
            float n  = __shfl_up_sync(FULL, w, o);
            float np = __shfl_up_sync(FULL, pw, o);
            if (lane >= o) { w += n; pw += np; }
        }
        float e  = __shfl_up_sync(FULL, w, 1);
        float ep = __shfl_up_sync(FULL, pw, 1);
        if (lane == 0) { e = 0.0f; ep = 0.0f; }
        float ts  = (lane < 16) ? sTr[lane] : 0.0f;
        float bmn = (lane < 16) ? e + sMnA[lane] : 3.4e38f;
        float bmx = (lane < 16) ? e + sMxA[lane] : -3.4e38f;
#pragma unroll
        for (int o = 16; o > 0; o >>= 1) {
            ts  += __shfl_down_sync(FULL, ts, o);
            bmn = fminf(bmn, __shfl_down_sync(FULL, bmn, o));
            bmx = fmaxf(bmx, __shfl_down_sync(FULL, bmx, o));
        }
        if (lane < 16) { sWSe[lane] = e; sPSe[lane] = ep; }
        if (lane == 0) {
            sTmean = ts * (1.0f / TT);
            float mn  = fmaf(Q, 0.2f, bmn) - 1e-5f;
            float wdt = (bmx - bmn) + 2e-5f;
            sMn = mn;
            sInvD  = 31.0f / wdt;
            sDelta = wdt * (1.0f / 31.0f);
        }
    }
    __syncthreads();                                  // barrier #2

    // ---------- per-warp register table (OCV, th2); block constants C, R1C ----------
    float tabO, tabT, Cc, Rc;
    {
        float Tm = sTmean;
        float se = fmaf((float)lane, sDelta, sMn);
        float p0 = sB2[0], p1 = sB2[1], p2 = sB2[2], p5 = sB2[3], p6 = sB2[4];
#pragma unroll
        for (int j = 0; j < 6; j++) {
            float c1 = fmaf(R0, W1g[6 + j], fmaf(Tm, W1g[12 + j], b1g[j]));
            float h = softplus_f(fmaf(se, sW10[j], c1));
            p0 = fmaf(h, sW2[j * 5 + 0], p0);
            p1 = fmaf(h, sW2[j * 5 + 1], p1);
            p2 = fmaf(h, sW2[j * 5 + 2], p2);
            p5 = fmaf(h, sW2[j * 5 + 3], p5);
            p6 = fmaf(h, sW2[j * 5 + 4], p6);
        }
        float R1 = 0.04f * sigmoid_f(0.01f * p0);
        float C  = 1e-6f * sigmoid_f(0.01f * p1);
        tabT = fmaf(0.75f, sigmoid_f(0.01f * p2), 0.05f);
        float ox = fmaf(0.79764f, sigmoid_f(0.01f * p5), 0.04236f);
        float oy = fmaf(0.82504f, sigmoid_f(0.01f * p6), 0.023f);

        float up = 4.4167f + oy * (-1.6518f + oy * (1.6225f + oy * (-2.0843f + oy * (3.5146f + oy * (-2.2166f)))));
        up -= 4.0f * __expf(fmaf(109.451f, oy, -100.006f));
        float un = 0.063f + 0.8f * __expf(-75.0f * (ox + 0.001f));
        un -= 0.012f  * tanh_fast(fmaf(ox, 62.5f, -7.9375f));
        un -= 0.0118f * tanh_fast(fmaf(ox, 62.5f, -9.6875f));
        un -= 0.0035f * tanh_fast(fmaf(ox, 50.0f, -11.0f));
        un -= 0.0095f * tanh_fast(fmaf(ox, 76.923076923f, -14.6153846154f));
        un -= 0.0145f * tanh_fast(fmaf(ox, 50.0f, -24.5f));
        un -= 0.08f   * tanh_fast(fmaf(ox, 18.1818181818f, -18.7272727273f));
        tabO = up - un;

        Cc = __shfl_sync(FULL, C, 15);                // mid-range -> block constant
        Rc = __shfl_sync(FULL, R1 * C, 15);
    }

    // ---------- pointwise finalize (per-thread OCV linearization) ----------
    const float mn = sMn, invD = sInvD;
    const float I0 = sI0;
    float U10;
    {   // th2 at soc0 from table (soc0 = Q/QN, inside range)
        int i0 = __float2int_rn((Q * 0.2f - mn) * invD);
        i0 = max(0, min(31, i0));
        float th2 = __shfl_sync(FULL, tabT, i0);
        U10 = -th2 - I0 * R0;
    }
    const float start = fmaf(Q, 0.2f, sWSe[wid] + excl);
    const float Sbase = sPSe[wid] + pexcl;
    const float uc = U10 * Cc;                 // U1 = U10 - uc*(I-I0) + Rc*(Sbase+s)
    const float cI = R0 - uc;                  // coefficient of I_k
    // thread-local OCV line: O(start + r) ~= O0 + slD*r
    float O0, slD;
    {
        float u = (start - mn) * invD;         // in [0, 31]
        int i = (int)u;
        i = max(0, min(30, i));
        float f0 = __shfl_sync(FULL, tabO, i);
        float f1 = __shfl_sync(FULL, tabO, i + 1);
        float df = f1 - f0;
        O0  = fmaf(u - (float)i, df, f0);
        slD = df * invD;
    }
    const float c0 = U10 + uc * I0 + Rc * Sbase + O0;
    float* rg = raw + wid * REG;
#pragma unroll
    for (int k = 0; k < LL; k++) {
        float2 rr = __half22float2(rh[k >> 1]);
        float rk = (k & 1) ? rr.y : rr.x;
        float2 ss = __half22float2(sh[k >> 1]);
        float sk = (k & 1) ? ss.y : ss.x;
        rg[vslot(lane * LL + k)] =
            fmaf(rk, slD, fmaf(I[k], cI, fmaf(Rc, sk, c0)));
    }
    __syncwarp();

    // ---------- warp-local transpose out: LDS.128 + STG.128, fully coalesced ----------
    float* ob = out + (size_t)b * TT + wid * 512;
#pragma unroll
    for (int j = 0; j < 4; j++) {
        int x = 4 * lane + 128 * j;
        float4 w = *reinterpret_cast<float4*>(&rg[vslot(x)]);
        *reinterpret_cast<float4*>(ob + x) = w;
    }
}

extern "C" void kernel_launch(void* const* d_in, const int* in_sizes, int n_in,
                              void* d_out, int out_size)
{
    const float* X  = (const float*)d_in[0];
    const float* SC = (const float*)d_in[1];
    const float* W1 = (const float*)d_in[2];
    const float* b1 = (const float*)d_in[3];
    const float* W2 = (const float*)d_in[4];
    const float* b2 = (const float*)d_in[5];
    int B = in_sizes[1] / 2;   // SC is (B,2)
    cudaFuncSetAttribute(voltage_kernel,
                         cudaFuncAttributeMaxDynamicSharedMemorySize, SMEM_BYTES);
    voltage_kernel<<<B, NT, SMEM_BYTES>>>(X, SC, W1, b1, W2, b2, (float*)d_out);
}